// round 1
// baseline (speedup 1.0000x reference)
#include <cuda_runtime.h>

#define D_MODEL 1024
#define NHEADS  16
#define DK      64
#define BATCH   2
#define SEQ     2048
#define MTOT    (BATCH * SEQ)   // 4096

// Scratch (device globals — no allocation allowed)
__device__ float g_q[(size_t)BATCH * NHEADS * SEQ * DK];   // [B,H,S,DK]
__device__ float g_k[(size_t)BATCH * NHEADS * SEQ * DK];
__device__ float g_v[(size_t)BATCH * NHEADS * SEQ * DK];
__device__ float g_ctx[(size_t)MTOT * D_MODEL];            // [B*S, D]

// ---------------------------------------------------------------------------
// GEMM: out = A[M,K] @ W[K,N] + bias   (M=4096, N=K=1024 fixed)
// BM=64, BN=64, BK=16, 256 threads, 4x4 microtile per thread.
// split_heads=1: write out[((b*H+h)*S+s)*DK + d] instead of [m*N+n]
// ---------------------------------------------------------------------------
__global__ __launch_bounds__(256) void gemm_kernel(
    const float* __restrict__ A, const float* __restrict__ W,
    const float* __restrict__ bias, float* __restrict__ out, int split_heads)
{
    __shared__ float As[64][16];
    __shared__ float Ws[16][64];

    const int tid = threadIdx.x;
    const int tx = tid & 15;
    const int ty = tid >> 4;
    const int m0 = blockIdx.y * 64;
    const int n0 = blockIdx.x * 64;

    float acc[4][4] = {};

    for (int k0 = 0; k0 < D_MODEL; k0 += 16) {
        // Load A tile 64x16: one float4 per thread
        {
            int row = tid >> 2;
            int c4  = tid & 3;
            float4 v = *(const float4*)&A[(size_t)(m0 + row) * D_MODEL + k0 + c4 * 4];
            *(float4*)&As[row][c4 * 4] = v;
        }
        // Load W tile 16x64: one float4 per thread
        {
            int row = tid >> 4;
            int c4  = tid & 15;
            float4 v = *(const float4*)&W[(size_t)(k0 + row) * D_MODEL + n0 + c4 * 4];
            *(float4*)&Ws[row][c4 * 4] = v;
        }
        __syncthreads();

        #pragma unroll
        for (int kk = 0; kk < 16; kk++) {
            float4 wv = *(const float4*)&Ws[kk][tx * 4];
            #pragma unroll
            for (int i = 0; i < 4; i++) {
                float a = As[ty * 4 + i][kk];
                acc[i][0] += a * wv.x;
                acc[i][1] += a * wv.y;
                acc[i][2] += a * wv.z;
                acc[i][3] += a * wv.w;
            }
        }
        __syncthreads();
    }

    #pragma unroll
    for (int i = 0; i < 4; i++) {
        int m = m0 + ty * 4 + i;
        int b = m / SEQ;
        int s = m % SEQ;
        #pragma unroll
        for (int j = 0; j < 4; j++) {
            int n = n0 + tx * 4 + j;
            float v = acc[i][j] + bias[n];
            if (split_heads) {
                int h = n >> 6;      // n / DK
                int d = n & 63;      // n % DK
                out[(((size_t)(b * NHEADS + h) * SEQ) + s) * DK + d] = v;
            } else {
                out[(size_t)m * D_MODEL + n] = v;
            }
        }
    }
}

// ---------------------------------------------------------------------------
// Flash attention: per (b,h), 64-query tile per block, iterate 64-key tiles.
// Q/K/V in [B,H,S,DK] layout. Writes ctx in [B*S, D_MODEL] layout.
// Dynamic smem: Qs(64x64) + Kt(64x68, transposed K) + Vs(64x64) + Ps(64x64)
// ---------------------------------------------------------------------------
#define KT_STRIDE 68

__global__ __launch_bounds__(256) void attn_kernel(
    const float* __restrict__ Q, const float* __restrict__ K,
    const float* __restrict__ V, float* __restrict__ ctx)
{
    extern __shared__ float sm[];
    float* Qs = sm;                           // 64*64
    float* Kt = Qs + 64 * DK;                 // 64(d) x KT_STRIDE, [d][kc]
    float* Vs = Kt + DK * KT_STRIDE;          // 64*64, [kc][d]
    float* Ps = Vs + 64 * DK;                 // 64*64, [q][kc]

    const int tid = threadIdx.x;
    const int tx = tid & 15;
    const int ty = tid >> 4;
    const int bh = blockIdx.y;                // 0..B*H-1
    const int q0 = blockIdx.x * 64;

    const float* Qb = Q + (size_t)bh * SEQ * DK;
    const float* Kb = K + (size_t)bh * SEQ * DK;
    const float* Vb = V + (size_t)bh * SEQ * DK;

    // Load Q tile, fold in softmax scale 1/sqrt(64) = 0.125
    #pragma unroll
    for (int r = 0; r < 4; r++) {
        int idx = tid + r * 256;              // 1024 float4s
        int row = idx >> 4;
        int c4  = idx & 15;
        float4 qv = *(const float4*)&Qb[(size_t)(q0 + row) * DK + c4 * 4];
        qv.x *= 0.125f; qv.y *= 0.125f; qv.z *= 0.125f; qv.w *= 0.125f;
        *(float4*)&Qs[row * DK + c4 * 4] = qv;
    }

    float acc[4][4] = {};
    float mrow[4], lrow[4];
    #pragma unroll
    for (int i = 0; i < 4; i++) { mrow[i] = -1e30f; lrow[i] = 0.0f; }

    for (int kb = 0; kb < SEQ; kb += 64) {
        __syncthreads();  // protect Kt/Vs/Ps from previous iteration readers

        // Load K tile transposed into Kt[d][kc], V tile direct into Vs[kc][d]
        #pragma unroll
        for (int r = 0; r < 4; r++) {
            int idx = tid + r * 256;
            int kc = idx >> 4;
            int c4 = idx & 15;
            float4 kv = *(const float4*)&Kb[(size_t)(kb + kc) * DK + c4 * 4];
            Kt[(c4 * 4 + 0) * KT_STRIDE + kc] = kv.x;
            Kt[(c4 * 4 + 1) * KT_STRIDE + kc] = kv.y;
            Kt[(c4 * 4 + 2) * KT_STRIDE + kc] = kv.z;
            Kt[(c4 * 4 + 3) * KT_STRIDE + kc] = kv.w;
            float4 vv = *(const float4*)&Vb[(size_t)(kb + kc) * DK + c4 * 4];
            *(float4*)&Vs[kc * DK + c4 * 4] = vv;
        }
        __syncthreads();

        // Scores: s[i][j] = Q[q0+ty*4+i] . K[kb+tx*4+j]  (Q pre-scaled)
        float s[4][4] = {};
        #pragma unroll
        for (int d4 = 0; d4 < 16; d4++) {
            float4 kd[4];
            #pragma unroll
            for (int e = 0; e < 4; e++)
                kd[e] = *(const float4*)&Kt[(d4 * 4 + e) * KT_STRIDE + tx * 4];
            float4 qv[4];
            #pragma unroll
            for (int i = 0; i < 4; i++)
                qv[i] = *(const float4*)&Qs[(ty * 4 + i) * DK + d4 * 4];
            #pragma unroll
            for (int i = 0; i < 4; i++) {
                const float* kp0 = (const float*)&kd[0];
                const float* kp1 = (const float*)&kd[1];
                const float* kp2 = (const float*)&kd[2];
                const float* kp3 = (const float*)&kd[3];
                #pragma unroll
                for (int j = 0; j < 4; j++) {
                    s[i][j] += qv[i].x * kp0[j];
                    s[i][j] += qv[i].y * kp1[j];
                    s[i][j] += qv[i].z * kp2[j];
                    s[i][j] += qv[i].w * kp3[j];
                }
            }
        }

        // Online softmax: row reductions across the 16 tx lanes (same half-warp)
        #pragma unroll
        for (int i = 0; i < 4; i++) {
            float mloc = fmaxf(fmaxf(s[i][0], s[i][1]), fmaxf(s[i][2], s[i][3]));
            #pragma unroll
            for (int off = 8; off; off >>= 1)
                mloc = fmaxf(mloc, __shfl_xor_sync(0xffffffffu, mloc, off));
            float mnew = fmaxf(mrow[i], mloc);
            float corr = __expf(mrow[i] - mnew);
            float p0 = __expf(s[i][0] - mnew);
            float p1 = __expf(s[i][1] - mnew);
            float p2 = __expf(s[i][2] - mnew);
            float p3 = __expf(s[i][3] - mnew);
            float lloc = (p0 + p1) + (p2 + p3);
            #pragma unroll
            for (int off = 8; off; off >>= 1)
                lloc += __shfl_xor_sync(0xffffffffu, lloc, off);
            lrow[i] = lrow[i] * corr + lloc;
            mrow[i] = mnew;
            acc[i][0] *= corr; acc[i][1] *= corr;
            acc[i][2] *= corr; acc[i][3] *= corr;
            float4 pq = make_float4(p0, p1, p2, p3);
            *(float4*)&Ps[(ty * 4 + i) * 64 + tx * 4] = pq;
        }
        __syncthreads();

        // O += P @ V : acc[i][j] += sum_kk Ps[q][kk] * Vs[kk][d]
        #pragma unroll
        for (int k4 = 0; k4 < 16; k4++) {
            float4 vv[4];
            #pragma unroll
            for (int e = 0; e < 4; e++)
                vv[e] = *(const float4*)&Vs[(k4 * 4 + e) * DK + tx * 4];
            #pragma unroll
            for (int i = 0; i < 4; i++) {
                float4 pv = *(const float4*)&Ps[(ty * 4 + i) * 64 + k4 * 4];
                const float* v0 = (const float*)&vv[0];
                const float* v1 = (const float*)&vv[1];
                const float* v2 = (const float*)&vv[2];
                const float* v3 = (const float*)&vv[3];
                #pragma unroll
                for (int j = 0; j < 4; j++) {
                    acc[i][j] += pv.x * v0[j];
                    acc[i][j] += pv.y * v1[j];
                    acc[i][j] += pv.z * v2[j];
                    acc[i][j] += pv.w * v3[j];
                }
            }
        }
    }

    // Normalize and write ctx in [B*S, D_MODEL] layout (heads re-interleaved)
    const int b = bh >> 4;
    const int h = bh & 15;
    #pragma unroll
    for (int i = 0; i < 4; i++) {
        int qrow = q0 + ty * 4 + i;
        float inv = 1.0f / lrow[i];
        float4 o = make_float4(acc[i][0] * inv, acc[i][1] * inv,
                               acc[i][2] * inv, acc[i][3] * inv);
        *(float4*)&g_ctx[((size_t)(b * SEQ + qrow)) * D_MODEL + h * DK + tx * 4] = o;
    }
    (void)ctx;
}

// ---------------------------------------------------------------------------
extern "C" void kernel_launch(void* const* d_in, const int* in_sizes, int n_in,
                              void* d_out, int out_size)
{
    const float* q  = (const float*)d_in[0];
    const float* k  = (const float*)d_in[1];
    const float* v  = (const float*)d_in[2];
    const float* Wq = (const float*)d_in[3];
    const float* bq = (const float*)d_in[4];
    const float* Wk = (const float*)d_in[5];
    const float* bk = (const float*)d_in[6];
    const float* Wv = (const float*)d_in[7];
    const float* bv = (const float*)d_in[8];
    const float* Wo = (const float*)d_in[9];
    const float* bo = (const float*)d_in[10];
    float* out = (float*)d_out;

    float *gq, *gk, *gv, *gctx;
    cudaGetSymbolAddress((void**)&gq,   g_q);
    cudaGetSymbolAddress((void**)&gk,   g_k);
    cudaGetSymbolAddress((void**)&gv,   g_v);
    cudaGetSymbolAddress((void**)&gctx, g_ctx);

    dim3 ggrid(D_MODEL / 64, MTOT / 64);   // (16, 64)

    gemm_kernel<<<ggrid, 256>>>(q, Wq, bq, gq, 1);
    gemm_kernel<<<ggrid, 256>>>(k, Wk, bk, gk, 1);
    gemm_kernel<<<ggrid, 256>>>(v, Wv, bv, gv, 1);

    size_t asmem = (size_t)(64 * DK + DK * KT_STRIDE + 64 * DK + 64 * 64) * sizeof(float);
    cudaFuncSetAttribute(attn_kernel, cudaFuncAttributeMaxDynamicSharedMemorySize, (int)asmem);
    attn_kernel<<<dim3(SEQ / 64, BATCH * NHEADS), 256, asmem>>>(gq, gk, gv, gctx);

    gemm_kernel<<<ggrid, 256>>>(gctx, Wo, bo, out, 0);
}

// round 3
// speedup vs baseline: 1.3638x; 1.3638x over previous
#include <cuda_runtime.h>
#include <cuda_bf16.h>
#include <cstdint>

#define D_MODEL 1024
#define NHEADS  16
#define DK      64
#define BATCH   2
#define SEQ     2048
#define MTOT    (BATCH * SEQ)   // 4096

// ---------------------------------------------------------------------------
// Scratch (device globals — no allocation allowed)
// ---------------------------------------------------------------------------
__device__ float g_q[(size_t)BATCH * NHEADS * SEQ * DK];   // [B,H,S,DK]
__device__ float g_k[(size_t)BATCH * NHEADS * SEQ * DK];
__device__ float g_v[(size_t)BATCH * NHEADS * SEQ * DK];
__device__ float g_ctx[(size_t)MTOT * D_MODEL];            // [B*S, D]

__device__ __nv_bfloat16 g_ahi[(size_t)MTOT * D_MODEL];    // activation split
__device__ __nv_bfloat16 g_alo[(size_t)MTOT * D_MODEL];
__device__ __nv_bfloat16 g_whi[(size_t)D_MODEL * D_MODEL]; // weight^T split [N,K]
__device__ __nv_bfloat16 g_wlo[(size_t)D_MODEL * D_MODEL];

// ---------------------------------------------------------------------------
// helpers
// ---------------------------------------------------------------------------
__device__ __forceinline__ uint32_t smem_to_u32(const void* p) {
    uint32_t a;
    asm("{ .reg .u64 t; cvta.to.shared.u64 t, %1; cvt.u32.u64 %0, t; }"
        : "=r"(a) : "l"(p));
    return a;
}
__device__ __forceinline__ void cp_async16(uint32_t dst, const void* src) {
    asm volatile("cp.async.cg.shared.global [%0], [%1], 16;"
                 :: "r"(dst), "l"(src) : "memory");
}
#define CP_COMMIT() asm volatile("cp.async.commit_group;" ::: "memory")
#define CP_WAIT(n)  asm volatile("cp.async.wait_group %0;" :: "n"(n) : "memory")

__device__ __forceinline__ void ldsm_x4(uint32_t* d, uint32_t addr) {
    asm volatile("ldmatrix.sync.aligned.m8n8.x4.shared.b16 {%0,%1,%2,%3}, [%4];"
                 : "=r"(d[0]), "=r"(d[1]), "=r"(d[2]), "=r"(d[3]) : "r"(addr));
}
__device__ __forceinline__ void mma16816(float* c, const uint32_t* a,
                                         uint32_t b0, uint32_t b1) {
    asm volatile(
        "mma.sync.aligned.m16n8k16.row.col.f32.bf16.bf16.f32 "
        "{%0,%1,%2,%3}, {%4,%5,%6,%7}, {%8,%9}, {%0,%1,%2,%3};"
        : "+f"(c[0]), "+f"(c[1]), "+f"(c[2]), "+f"(c[3])
        : "r"(a[0]), "r"(a[1]), "r"(a[2]), "r"(a[3]), "r"(b0), "r"(b1));
}

// ---------------------------------------------------------------------------
// fp32 -> bf16 hi/lo split (elementwise)
// ---------------------------------------------------------------------------
__global__ __launch_bounds__(256) void conv_split(
    const float4* __restrict__ x, __nv_bfloat16* __restrict__ hi,
    __nv_bfloat16* __restrict__ lo, int n4)
{
    int i = blockIdx.x * 256 + threadIdx.x;
    if (i >= n4) return;
    float4 v = x[i];
    __nv_bfloat16 h[4], l[4];
    float f[4] = {v.x, v.y, v.z, v.w};
    #pragma unroll
    for (int e = 0; e < 4; e++) {
        h[e] = __float2bfloat16(f[e]);
        l[e] = __float2bfloat16(f[e] - __bfloat162float(h[e]));
    }
    *(uint2*)&hi[(size_t)i * 4] = *(uint2*)h;
    *(uint2*)&lo[(size_t)i * 4] = *(uint2*)l;
}

// W [K,N] fp32 -> W^T [N,K] bf16 hi/lo
__global__ __launch_bounds__(1024) void conv_wt(
    const float* __restrict__ W, __nv_bfloat16* __restrict__ hi,
    __nv_bfloat16* __restrict__ lo)
{
    __shared__ float t[32][33];
    int tx = threadIdx.x, ty = threadIdx.y;
    int n0 = blockIdx.x * 32, k0 = blockIdx.y * 32;
    t[ty][tx] = W[(size_t)(k0 + ty) * D_MODEL + n0 + tx];
    __syncthreads();
    float v = t[tx][ty];
    __nv_bfloat16 h = __float2bfloat16(v);
    size_t o = (size_t)(n0 + ty) * D_MODEL + k0 + tx;
    hi[o] = h;
    lo[o] = __float2bfloat16(v - __bfloat162float(h));
}

// ---------------------------------------------------------------------------
// bf16x3 tensor-core GEMM via mma.sync (HMMA path; tcgen05 not available at
// the harness's compute_103 PTX target).
// out[M=4096,N=1024] = (ahi+alo)[M,K] @ (whi+wlo)[N,K]^T + bias
// CTA 128x128, 8 warps 4(m)x2(n), warp tile 32x64, K-stage 32,
// cp.async double buffer. smem tile stride 40 bf16 (conflict-free ldmatrix).
// ---------------------------------------------------------------------------
#define GSTAGE 40960            // bytes per stage (4 tiles x 128 x 40 bf16)
#define OFF_AHI 0
#define OFF_ALO 10240
#define OFF_BHI 20480
#define OFF_BLO 30720
#define NSTAGES 32              // 1024 / 32

__global__ __launch_bounds__(256) void gemm_mma(
    const __nv_bfloat16* __restrict__ a_hi, const __nv_bfloat16* __restrict__ a_lo,
    const __nv_bfloat16* __restrict__ b_hi, const __nv_bfloat16* __restrict__ b_lo,
    const float* __restrict__ bias, float* __restrict__ outp, int split)
{
    extern __shared__ char smem[];
    const uint32_t sbase = smem_to_u32(smem);
    const int tid  = threadIdx.x;
    const int wid  = tid >> 5;
    const int lane = tid & 31;
    const int wm = wid >> 1;          // 0..3 -> m offset 32*wm
    const int wn = wid & 1;           // 0..1 -> n offset 64*wn
    const int m0 = blockIdx.y * 128;
    const int n0 = blockIdx.x * 128;

    const uint4* gAhi = (const uint4*)a_hi;
    const uint4* gAlo = (const uint4*)a_lo;
    const uint4* gBhi = (const uint4*)b_hi;
    const uint4* gBlo = (const uint4*)b_lo;

    // ---- async stage loader: 8 cp.async of 16B per thread -----------------
    auto load_stage = [&](int s) {
        const uint32_t stb = sbase + (uint32_t)(s & 1) * GSTAGE;
        const int koff4 = s * 4;  // 32 bf16 = 4 uint4 per row chunk
        #pragma unroll
        for (int t = 0; t < 2; t++) {
            int id = tid + (t << 8);          // 0..511
            int row = id >> 2;
            int c   = id & 3;
            uint32_t d = stb + row * 80 + c * 16;
            size_t srcA = (size_t)(m0 + row) * 128 + koff4 + c;
            size_t srcB = (size_t)(n0 + row) * 128 + koff4 + c;
            cp_async16(d + OFF_AHI, gAhi + srcA);
            cp_async16(d + OFF_ALO, gAlo + srcA);
            cp_async16(d + OFF_BHI, gBhi + srcB);
            cp_async16(d + OFF_BLO, gBlo + srcB);
        }
        CP_COMMIT();
    };

    float acc[2][8][4];
    #pragma unroll
    for (int i = 0; i < 2; i++)
        #pragma unroll
        for (int j = 0; j < 8; j++)
            #pragma unroll
            for (int e = 0; e < 4; e++) acc[i][j][e] = 0.0f;

    // ldmatrix lane address components
    const int lj = lane >> 3;     // matrix index 0..3
    const int lr = lane & 7;      // row within matrix

    load_stage(0);

    for (int s = 0; s < NSTAGES; s++) {
        if (s + 1 < NSTAGES) load_stage(s + 1);
        if (s + 1 < NSTAGES) { CP_WAIT(1); } else { CP_WAIT(0); }
        __syncthreads();

        const uint32_t stb = sbase + (uint32_t)(s & 1) * GSTAGE;

        #pragma unroll
        for (int t = 0; t < 2; t++) {          // two k16 ticks per stage
            const int kb = t * 16;
            // B fragments: 4 groups of n16 -> 8 n8-fragments (hi and lo)
            uint32_t bhi[4][4], blo[4][4];
            #pragma unroll
            for (int g = 0; g < 4; g++) {
                int brow = wn * 64 + g * 16 + ((lj >> 1) << 3) + lr;
                int bcol = kb + ((lj & 1) << 3);
                uint32_t ba = stb + brow * 80 + bcol * 2;
                ldsm_x4(bhi[g], ba + OFF_BHI);
                ldsm_x4(blo[g], ba + OFF_BLO);
            }
            // A hi fragments: 2 m16 frags
            uint32_t a[2][4];
            {
                int acol = kb + ((lj >> 1) << 3);
                #pragma unroll
                for (int fm = 0; fm < 2; fm++) {
                    int arow = wm * 32 + fm * 16 + ((lj & 1) << 3) + lr;
                    ldsm_x4(a[fm], stb + OFF_AHI + arow * 80 + acol * 2);
                }
            }
            #pragma unroll
            for (int fm = 0; fm < 2; fm++)
                #pragma unroll
                for (int g = 0; g < 4; g++) {
                    mma16816(acc[fm][g * 2 + 0], a[fm], bhi[g][0], bhi[g][1]);
                    mma16816(acc[fm][g * 2 + 1], a[fm], bhi[g][2], bhi[g][3]);
                    mma16816(acc[fm][g * 2 + 0], a[fm], blo[g][0], blo[g][1]);
                    mma16816(acc[fm][g * 2 + 1], a[fm], blo[g][2], blo[g][3]);
                }
            // A lo fragments (reuse regs)
            {
                int acol = kb + ((lj >> 1) << 3);
                #pragma unroll
                for (int fm = 0; fm < 2; fm++) {
                    int arow = wm * 32 + fm * 16 + ((lj & 1) << 3) + lr;
                    ldsm_x4(a[fm], stb + OFF_ALO + arow * 80 + acol * 2);
                }
            }
            #pragma unroll
            for (int fm = 0; fm < 2; fm++)
                #pragma unroll
                for (int g = 0; g < 4; g++) {
                    mma16816(acc[fm][g * 2 + 0], a[fm], bhi[g][0], bhi[g][1]);
                    mma16816(acc[fm][g * 2 + 1], a[fm], bhi[g][2], bhi[g][3]);
                }
        }
        __syncthreads();
    }

    // ---- epilogue: bias add + store -----------------------------------
    const int qrow = lane >> 2;
    const int qcol = (lane & 3) * 2;
    #pragma unroll
    for (int fm = 0; fm < 2; fm++) {
        #pragma unroll
        for (int fn = 0; fn < 8; fn++) {
            int col = n0 + wn * 64 + fn * 8 + qcol;
            float2 bv = *(const float2*)&bias[col];
            #pragma unroll
            for (int half = 0; half < 2; half++) {
                int gm = m0 + wm * 32 + fm * 16 + qrow + half * 8;
                float2 o = make_float2(acc[fm][fn][half * 2 + 0] + bv.x,
                                       acc[fm][fn][half * 2 + 1] + bv.y);
                float* dst;
                if (split) {
                    int b = gm >> 11, ss = gm & 2047;
                    int h = col >> 6, d = col & 63;
                    dst = &outp[(((size_t)(b * NHEADS + h)) * SEQ + ss) * DK + d];
                } else {
                    dst = &outp[(size_t)gm * D_MODEL + col];
                }
                *(float2*)dst = o;
            }
        }
    }
}

// ---------------------------------------------------------------------------
// Flash attention (unchanged, fp32 SIMT, 64q x 64k tiles)
// ---------------------------------------------------------------------------
#define KT_STRIDE 68

__global__ __launch_bounds__(256) void attn_kernel(
    const float* __restrict__ Q, const float* __restrict__ K,
    const float* __restrict__ V, float* __restrict__ ctx)
{
    extern __shared__ float sm[];
    float* Qs = sm;
    float* Kt = Qs + 64 * DK;
    float* Vs = Kt + DK * KT_STRIDE;
    float* Ps = Vs + 64 * DK;

    const int tid = threadIdx.x;
    const int tx = tid & 15;
    const int ty = tid >> 4;
    const int bh = blockIdx.y;
    const int q0 = blockIdx.x * 64;

    const float* Qb = Q + (size_t)bh * SEQ * DK;
    const float* Kb = K + (size_t)bh * SEQ * DK;
    const float* Vb = V + (size_t)bh * SEQ * DK;

    #pragma unroll
    for (int r = 0; r < 4; r++) {
        int idx = tid + r * 256;
        int row = idx >> 4;
        int c4  = idx & 15;
        float4 qv = *(const float4*)&Qb[(size_t)(q0 + row) * DK + c4 * 4];
        qv.x *= 0.125f; qv.y *= 0.125f; qv.z *= 0.125f; qv.w *= 0.125f;
        *(float4*)&Qs[row * DK + c4 * 4] = qv;
    }

    float acc[4][4] = {};
    float mrow[4], lrow[4];
    #pragma unroll
    for (int i = 0; i < 4; i++) { mrow[i] = -1e30f; lrow[i] = 0.0f; }

    for (int kb = 0; kb < SEQ; kb += 64) {
        __syncthreads();
        #pragma unroll
        for (int r = 0; r < 4; r++) {
            int idx = tid + r * 256;
            int kc = idx >> 4;
            int c4 = idx & 15;
            float4 kv = *(const float4*)&Kb[(size_t)(kb + kc) * DK + c4 * 4];
            Kt[(c4 * 4 + 0) * KT_STRIDE + kc] = kv.x;
            Kt[(c4 * 4 + 1) * KT_STRIDE + kc] = kv.y;
            Kt[(c4 * 4 + 2) * KT_STRIDE + kc] = kv.z;
            Kt[(c4 * 4 + 3) * KT_STRIDE + kc] = kv.w;
            float4 vv = *(const float4*)&Vb[(size_t)(kb + kc) * DK + c4 * 4];
            *(float4*)&Vs[kc * DK + c4 * 4] = vv;
        }
        __syncthreads();

        float s[4][4] = {};
        #pragma unroll
        for (int d4 = 0; d4 < 16; d4++) {
            float4 kd[4];
            #pragma unroll
            for (int e = 0; e < 4; e++)
                kd[e] = *(const float4*)&Kt[(d4 * 4 + e) * KT_STRIDE + tx * 4];
            float4 qv[4];
            #pragma unroll
            for (int i = 0; i < 4; i++)
                qv[i] = *(const float4*)&Qs[(ty * 4 + i) * DK + d4 * 4];
            #pragma unroll
            for (int i = 0; i < 4; i++) {
                const float* kp0 = (const float*)&kd[0];
                const float* kp1 = (const float*)&kd[1];
                const float* kp2 = (const float*)&kd[2];
                const float* kp3 = (const float*)&kd[3];
                #pragma unroll
                for (int j = 0; j < 4; j++) {
                    s[i][j] += qv[i].x * kp0[j];
                    s[i][j] += qv[i].y * kp1[j];
                    s[i][j] += qv[i].z * kp2[j];
                    s[i][j] += qv[i].w * kp3[j];
                }
            }
        }

        #pragma unroll
        for (int i = 0; i < 4; i++) {
            float mloc = fmaxf(fmaxf(s[i][0], s[i][1]), fmaxf(s[i][2], s[i][3]));
            #pragma unroll
            for (int off = 8; off; off >>= 1)
                mloc = fmaxf(mloc, __shfl_xor_sync(0xffffffffu, mloc, off));
            float mnew = fmaxf(mrow[i], mloc);
            float corr = __expf(mrow[i] - mnew);
            float p0 = __expf(s[i][0] - mnew);
            float p1 = __expf(s[i][1] - mnew);
            float p2 = __expf(s[i][2] - mnew);
            float p3 = __expf(s[i][3] - mnew);
            float lloc = (p0 + p1) + (p2 + p3);
            #pragma unroll
            for (int off = 8; off; off >>= 1)
                lloc += __shfl_xor_sync(0xffffffffu, lloc, off);
            lrow[i] = lrow[i] * corr + lloc;
            mrow[i] = mnew;
            acc[i][0] *= corr; acc[i][1] *= corr;
            acc[i][2] *= corr; acc[i][3] *= corr;
            float4 pq = make_float4(p0, p1, p2, p3);
            *(float4*)&Ps[(ty * 4 + i) * 64 + tx * 4] = pq;
        }
        __syncthreads();

        #pragma unroll
        for (int k4 = 0; k4 < 16; k4++) {
            float4 vv[4];
            #pragma unroll
            for (int e = 0; e < 4; e++)
                vv[e] = *(const float4*)&Vs[(k4 * 4 + e) * DK + tx * 4];
            #pragma unroll
            for (int i = 0; i < 4; i++) {
                float4 pv = *(const float4*)&Ps[(ty * 4 + i) * 64 + k4 * 4];
                const float* v0 = (const float*)&vv[0];
                const float* v1 = (const float*)&vv[1];
                const float* v2 = (const float*)&vv[2];
                const float* v3 = (const float*)&vv[3];
                #pragma unroll
                for (int j = 0; j < 4; j++) {
                    acc[i][j] += pv.x * v0[j];
                    acc[i][j] += pv.y * v1[j];
                    acc[i][j] += pv.z * v2[j];
                    acc[i][j] += pv.w * v3[j];
                }
            }
        }
    }

    const int b = bh >> 4;
    const int h = bh & 15;
    #pragma unroll
    for (int i = 0; i < 4; i++) {
        int qrow = q0 + ty * 4 + i;
        float inv = 1.0f / lrow[i];
        float4 o = make_float4(acc[i][0] * inv, acc[i][1] * inv,
                               acc[i][2] * inv, acc[i][3] * inv);
        *(float4*)&g_ctx[((size_t)(b * SEQ + qrow)) * D_MODEL + h * DK + tx * 4] = o;
    }
    (void)ctx;
}

// ---------------------------------------------------------------------------
extern "C" void kernel_launch(void* const* d_in, const int* in_sizes, int n_in,
                              void* d_out, int out_size)
{
    const float* q  = (const float*)d_in[0];
    const float* k  = (const float*)d_in[1];
    const float* v  = (const float*)d_in[2];
    const float* Wq = (const float*)d_in[3];
    const float* bq = (const float*)d_in[4];
    const float* Wk = (const float*)d_in[5];
    const float* bk = (const float*)d_in[6];
    const float* Wv = (const float*)d_in[7];
    const float* bv = (const float*)d_in[8];
    const float* Wo = (const float*)d_in[9];
    const float* bo = (const float*)d_in[10];
    float* out = (float*)d_out;

    float *gq, *gk, *gv, *gctx;
    __nv_bfloat16 *ahi, *alo, *whi, *wlo;
    cudaGetSymbolAddress((void**)&gq,   g_q);
    cudaGetSymbolAddress((void**)&gk,   g_k);
    cudaGetSymbolAddress((void**)&gv,   g_v);
    cudaGetSymbolAddress((void**)&gctx, g_ctx);
    cudaGetSymbolAddress((void**)&ahi,  g_ahi);
    cudaGetSymbolAddress((void**)&alo,  g_alo);
    cudaGetSymbolAddress((void**)&whi,  g_whi);
    cudaGetSymbolAddress((void**)&wlo,  g_wlo);

    const int actN4 = MTOT * D_MODEL / 4;
    const dim3 wtGrid(D_MODEL / 32, D_MODEL / 32);
    const dim3 wtBlk(32, 32);
    const dim3 gemmGrid(D_MODEL / 128, MTOT / 128);   // (8, 32)
    const size_t gemmSmem = 2 * GSTAGE;               // 81920 B

    cudaFuncSetAttribute(gemm_mma, cudaFuncAttributeMaxDynamicSharedMemorySize, (int)gemmSmem);

    // Q projection
    conv_wt<<<wtGrid, wtBlk>>>(Wq, whi, wlo);
    conv_split<<<(actN4 + 255) / 256, 256>>>((const float4*)q, ahi, alo, actN4);
    gemm_mma<<<gemmGrid, 256, gemmSmem>>>(ahi, alo, whi, wlo, bq, gq, 1);
    // K projection
    conv_wt<<<wtGrid, wtBlk>>>(Wk, whi, wlo);
    conv_split<<<(actN4 + 255) / 256, 256>>>((const float4*)k, ahi, alo, actN4);
    gemm_mma<<<gemmGrid, 256, gemmSmem>>>(ahi, alo, whi, wlo, bk, gk, 1);
    // V projection
    conv_wt<<<wtGrid, wtBlk>>>(Wv, whi, wlo);
    conv_split<<<(actN4 + 255) / 256, 256>>>((const float4*)v, ahi, alo, actN4);
    gemm_mma<<<gemmGrid, 256, gemmSmem>>>(ahi, alo, whi, wlo, bv, gv, 1);

    // Attention (fp32 SIMT)
    size_t asmem = (size_t)(64 * DK + DK * KT_STRIDE + 64 * DK + 64 * 64) * sizeof(float);
    cudaFuncSetAttribute(attn_kernel, cudaFuncAttributeMaxDynamicSharedMemorySize, (int)asmem);
    attn_kernel<<<dim3(SEQ / 64, BATCH * NHEADS), 256, asmem>>>(gq, gk, gv, gctx);

    // Output projection
    conv_wt<<<wtGrid, wtBlk>>>(Wo, whi, wlo);
    conv_split<<<(actN4 + 255) / 256, 256>>>((const float4*)gctx, ahi, alo, actN4);
    gemm_mma<<<gemmGrid, 256, gemmSmem>>>(ahi, alo, whi, wlo, bo, out, 0);
}

// round 4
// speedup vs baseline: 2.4628x; 1.8059x over previous
#include <cuda_runtime.h>
#include <cuda_bf16.h>
#include <cstdint>

#define D_MODEL 1024
#define NHEADS  16
#define DK      64
#define BATCH   2
#define SEQ     2048
#define MTOT    (BATCH * SEQ)   // 4096

// ---------------------------------------------------------------------------
// Scratch (device globals — no allocation allowed)
// ---------------------------------------------------------------------------
__device__ __nv_bfloat16 g_ahi[(size_t)MTOT * D_MODEL];    // activation split in
__device__ __nv_bfloat16 g_alo[(size_t)MTOT * D_MODEL];
__device__ __nv_bfloat16 g_whi[(size_t)D_MODEL * D_MODEL]; // weight^T split [N,K]
__device__ __nv_bfloat16 g_wlo[(size_t)D_MODEL * D_MODEL];

__device__ __nv_bfloat16 g_qhi[(size_t)MTOT * DK * NHEADS]; // [B,H,S,DK]
__device__ __nv_bfloat16 g_qlo[(size_t)MTOT * DK * NHEADS];
__device__ __nv_bfloat16 g_khi[(size_t)MTOT * DK * NHEADS];
__device__ __nv_bfloat16 g_klo[(size_t)MTOT * DK * NHEADS];
__device__ __nv_bfloat16 g_vhi[(size_t)MTOT * DK * NHEADS];
__device__ __nv_bfloat16 g_vlo[(size_t)MTOT * DK * NHEADS];
__device__ __nv_bfloat16 g_chi[(size_t)MTOT * D_MODEL];    // ctx split [M, D]
__device__ __nv_bfloat16 g_clo[(size_t)MTOT * D_MODEL];

// ---------------------------------------------------------------------------
// helpers
// ---------------------------------------------------------------------------
__device__ __forceinline__ uint32_t smem_to_u32(const void* p) {
    uint32_t a;
    asm("{ .reg .u64 t; cvta.to.shared.u64 t, %1; cvt.u32.u64 %0, t; }"
        : "=r"(a) : "l"(p));
    return a;
}
__device__ __forceinline__ void cp_async16(uint32_t dst, const void* src) {
    asm volatile("cp.async.cg.shared.global [%0], [%1], 16;"
                 :: "r"(dst), "l"(src) : "memory");
}
#define CP_COMMIT() asm volatile("cp.async.commit_group;" ::: "memory")
#define CP_WAIT(n)  asm volatile("cp.async.wait_group %0;" :: "n"(n) : "memory")

__device__ __forceinline__ void ldsm_x4(uint32_t* d, uint32_t addr) {
    asm volatile("ldmatrix.sync.aligned.m8n8.x4.shared.b16 {%0,%1,%2,%3}, [%4];"
                 : "=r"(d[0]), "=r"(d[1]), "=r"(d[2]), "=r"(d[3]) : "r"(addr));
}
__device__ __forceinline__ void ldsm_x4_t(uint32_t* d, uint32_t addr) {
    asm volatile("ldmatrix.sync.aligned.m8n8.x4.trans.shared.b16 {%0,%1,%2,%3}, [%4];"
                 : "=r"(d[0]), "=r"(d[1]), "=r"(d[2]), "=r"(d[3]) : "r"(addr));
}
__device__ __forceinline__ void mma16816(float* c, const uint32_t* a,
                                         uint32_t b0, uint32_t b1) {
    asm volatile(
        "mma.sync.aligned.m16n8k16.row.col.f32.bf16.bf16.f32 "
        "{%0,%1,%2,%3}, {%4,%5,%6,%7}, {%8,%9}, {%0,%1,%2,%3};"
        : "+f"(c[0]), "+f"(c[1]), "+f"(c[2]), "+f"(c[3])
        : "r"(a[0]), "r"(a[1]), "r"(a[2]), "r"(a[3]), "r"(b0), "r"(b1));
}
// split (x,y) into packed bf16 hi and lo pairs (low half = x)
__device__ __forceinline__ void split2(float x, float y, uint32_t& hi, uint32_t& lo) {
    __nv_bfloat16 hx = __float2bfloat16(x);
    __nv_bfloat16 hy = __float2bfloat16(y);
    __nv_bfloat16 lx = __float2bfloat16(x - __bfloat162float(hx));
    __nv_bfloat16 ly = __float2bfloat16(y - __bfloat162float(hy));
    hi = ((uint32_t)*(unsigned short*)&hy << 16) | (uint32_t)*(unsigned short*)&hx;
    lo = ((uint32_t)*(unsigned short*)&ly << 16) | (uint32_t)*(unsigned short*)&lx;
}

// ---------------------------------------------------------------------------
// fp32 -> bf16 hi/lo split (elementwise)
// ---------------------------------------------------------------------------
__global__ __launch_bounds__(256) void conv_split(
    const float4* __restrict__ x, __nv_bfloat16* __restrict__ hi,
    __nv_bfloat16* __restrict__ lo, int n4)
{
    int i = blockIdx.x * 256 + threadIdx.x;
    if (i >= n4) return;
    float4 v = x[i];
    __nv_bfloat16 h[4], l[4];
    float f[4] = {v.x, v.y, v.z, v.w};
    #pragma unroll
    for (int e = 0; e < 4; e++) {
        h[e] = __float2bfloat16(f[e]);
        l[e] = __float2bfloat16(f[e] - __bfloat162float(h[e]));
    }
    *(uint2*)&hi[(size_t)i * 4] = *(uint2*)h;
    *(uint2*)&lo[(size_t)i * 4] = *(uint2*)l;
}

// W [K,N] fp32 -> W^T [N,K] bf16 hi/lo
__global__ __launch_bounds__(1024) void conv_wt(
    const float* __restrict__ W, __nv_bfloat16* __restrict__ hi,
    __nv_bfloat16* __restrict__ lo)
{
    __shared__ float t[32][33];
    int tx = threadIdx.x, ty = threadIdx.y;
    int n0 = blockIdx.x * 32, k0 = blockIdx.y * 32;
    t[ty][tx] = W[(size_t)(k0 + ty) * D_MODEL + n0 + tx];
    __syncthreads();
    float v = t[tx][ty];
    __nv_bfloat16 h = __float2bfloat16(v);
    size_t o = (size_t)(n0 + ty) * D_MODEL + k0 + tx;
    hi[o] = h;
    lo[o] = __float2bfloat16(v - __bfloat162float(h));
}

// ---------------------------------------------------------------------------
// bf16x3 tensor-core GEMM. out = (ahi+alo)[M,K] @ (whi+wlo)[N,K]^T + bias
// If ohi != 0: write bf16 hi/lo, head-split [B,H,S,DK], scaled by `scale`.
// Else: fp32 row-major to outp.
// ---------------------------------------------------------------------------
#define GSTAGE 40960
#define OFF_AHI 0
#define OFF_ALO 10240
#define OFF_BHI 20480
#define OFF_BLO 30720
#define NSTAGES 32

__global__ __launch_bounds__(256) void gemm_mma(
    const __nv_bfloat16* __restrict__ a_hi, const __nv_bfloat16* __restrict__ a_lo,
    const __nv_bfloat16* __restrict__ b_hi, const __nv_bfloat16* __restrict__ b_lo,
    const float* __restrict__ bias, float* __restrict__ outp,
    __nv_bfloat16* __restrict__ ohi, __nv_bfloat16* __restrict__ olo, float scale)
{
    extern __shared__ char smem[];
    const uint32_t sbase = smem_to_u32(smem);
    const int tid  = threadIdx.x;
    const int wid  = tid >> 5;
    const int lane = tid & 31;
    const int wm = wid >> 1;
    const int wn = wid & 1;
    const int m0 = blockIdx.y * 128;
    const int n0 = blockIdx.x * 128;

    const uint4* gAhi = (const uint4*)a_hi;
    const uint4* gAlo = (const uint4*)a_lo;
    const uint4* gBhi = (const uint4*)b_hi;
    const uint4* gBlo = (const uint4*)b_lo;

    auto load_stage = [&](int s) {
        const uint32_t stb = sbase + (uint32_t)(s & 1) * GSTAGE;
        const int koff4 = s * 4;
        #pragma unroll
        for (int t = 0; t < 2; t++) {
            int id = tid + (t << 8);
            int row = id >> 2;
            int c   = id & 3;
            uint32_t d = stb + row * 80 + c * 16;
            size_t srcA = (size_t)(m0 + row) * 128 + koff4 + c;
            size_t srcB = (size_t)(n0 + row) * 128 + koff4 + c;
            cp_async16(d + OFF_AHI, gAhi + srcA);
            cp_async16(d + OFF_ALO, gAlo + srcA);
            cp_async16(d + OFF_BHI, gBhi + srcB);
            cp_async16(d + OFF_BLO, gBlo + srcB);
        }
        CP_COMMIT();
    };

    float acc[2][8][4];
    #pragma unroll
    for (int i = 0; i < 2; i++)
        #pragma unroll
        for (int j = 0; j < 8; j++)
            #pragma unroll
            for (int e = 0; e < 4; e++) acc[i][j][e] = 0.0f;

    const int lj = lane >> 3;
    const int lr = lane & 7;

    load_stage(0);

    for (int s = 0; s < NSTAGES; s++) {
        if (s + 1 < NSTAGES) load_stage(s + 1);
        if (s + 1 < NSTAGES) { CP_WAIT(1); } else { CP_WAIT(0); }
        __syncthreads();

        const uint32_t stb = sbase + (uint32_t)(s & 1) * GSTAGE;

        #pragma unroll
        for (int t = 0; t < 2; t++) {
            const int kb = t * 16;
            uint32_t bhi[4][4], blo[4][4];
            #pragma unroll
            for (int g = 0; g < 4; g++) {
                int brow = wn * 64 + g * 16 + ((lj >> 1) << 3) + lr;
                int bcol = kb + ((lj & 1) << 3);
                uint32_t ba = stb + brow * 80 + bcol * 2;
                ldsm_x4(bhi[g], ba + OFF_BHI);
                ldsm_x4(blo[g], ba + OFF_BLO);
            }
            uint32_t a[2][4];
            {
                int acol = kb + ((lj >> 1) << 3);
                #pragma unroll
                for (int fm = 0; fm < 2; fm++) {
                    int arow = wm * 32 + fm * 16 + ((lj & 1) << 3) + lr;
                    ldsm_x4(a[fm], stb + OFF_AHI + arow * 80 + acol * 2);
                }
            }
            #pragma unroll
            for (int fm = 0; fm < 2; fm++)
                #pragma unroll
                for (int g = 0; g < 4; g++) {
                    mma16816(acc[fm][g * 2 + 0], a[fm], bhi[g][0], bhi[g][1]);
                    mma16816(acc[fm][g * 2 + 1], a[fm], bhi[g][2], bhi[g][3]);
                    mma16816(acc[fm][g * 2 + 0], a[fm], blo[g][0], blo[g][1]);
                    mma16816(acc[fm][g * 2 + 1], a[fm], blo[g][2], blo[g][3]);
                }
            {
                int acol = kb + ((lj >> 1) << 3);
                #pragma unroll
                for (int fm = 0; fm < 2; fm++) {
                    int arow = wm * 32 + fm * 16 + ((lj & 1) << 3) + lr;
                    ldsm_x4(a[fm], stb + OFF_ALO + arow * 80 + acol * 2);
                }
            }
            #pragma unroll
            for (int fm = 0; fm < 2; fm++)
                #pragma unroll
                for (int g = 0; g < 4; g++) {
                    mma16816(acc[fm][g * 2 + 0], a[fm], bhi[g][0], bhi[g][1]);
                    mma16816(acc[fm][g * 2 + 1], a[fm], bhi[g][2], bhi[g][3]);
                }
        }
        __syncthreads();
    }

    // ---- epilogue --------------------------------------------------------
    const int qrow = lane >> 2;
    const int qcol = (lane & 3) * 2;
    #pragma unroll
    for (int fm = 0; fm < 2; fm++) {
        #pragma unroll
        for (int fn = 0; fn < 8; fn++) {
            int col = n0 + wn * 64 + fn * 8 + qcol;
            float2 bv = *(const float2*)&bias[col];
            #pragma unroll
            for (int half = 0; half < 2; half++) {
                int gm = m0 + wm * 32 + fm * 16 + qrow + half * 8;
                float x = (acc[fm][fn][half * 2 + 0] + bv.x) * scale;
                float y = (acc[fm][fn][half * 2 + 1] + bv.y) * scale;
                if (ohi) {
                    int b = gm >> 11, ss = gm & 2047;
                    int h = col >> 6, d = col & 63;
                    size_t off = (((size_t)(b * NHEADS + h)) * SEQ + ss) * DK + d;
                    uint32_t ph, pl;
                    split2(x, y, ph, pl);
                    *(uint32_t*)&ohi[off] = ph;
                    *(uint32_t*)&olo[off] = pl;
                } else {
                    *(float2*)&outp[(size_t)gm * D_MODEL + col] = make_float2(x, y);
                }
            }
        }
    }
}

// ---------------------------------------------------------------------------
// Tensor-core flash attention, bf16x3.
// CTA: 128 q rows, 8 warps (16 q rows each); kv tiles of 64, double-buffered.
// SMEM: Qhi 16K | Qlo 16K | 2 x (Khi 8K | Klo 8K | Vhi 8K | Vlo 8K)
// ---------------------------------------------------------------------------
#define AQ_HI 0
#define AQ_LO 16384
#define AKV0  32768
#define KVBUF 32768
#define ATT_SMEM (AKV0 + 2 * KVBUF)   // 98304

__global__ __launch_bounds__(256) void attn_mma(
    const __nv_bfloat16* __restrict__ qhi_, const __nv_bfloat16* __restrict__ qlo_,
    const __nv_bfloat16* __restrict__ khi_, const __nv_bfloat16* __restrict__ klo_,
    const __nv_bfloat16* __restrict__ vhi_, const __nv_bfloat16* __restrict__ vlo_,
    __nv_bfloat16* __restrict__ chi_, __nv_bfloat16* __restrict__ clo_)
{
    extern __shared__ char smem[];
    const uint32_t sb = smem_to_u32(smem);
    const int tid = threadIdx.x, wid = tid >> 5, lane = tid & 31;
    const int bh = blockIdx.y;
    const int q0 = blockIdx.x * 128;
    const size_t base = (size_t)bh * SEQ * DK;

    const uint4* gqh = (const uint4*)(qhi_ + base);
    const uint4* gql = (const uint4*)(qlo_ + base);
    const uint4* gkh = (const uint4*)(khi_ + base);
    const uint4* gkl = (const uint4*)(klo_ + base);
    const uint4* gvh = (const uint4*)(vhi_ + base);
    const uint4* gvl = (const uint4*)(vlo_ + base);

    // --- prologue: Q tile (128 rows x 8 chunks, swizzled) -------------------
    #pragma unroll
    for (int i = 0; i < 4; i++) {
        int id = tid + i * 256;
        int r = id >> 3, c = id & 7;
        uint32_t d = sb + AQ_HI + r * 128 + ((c ^ (r & 7)) << 4);
        size_t src = (size_t)(q0 + r) * 8 + c;
        cp_async16(d, gqh + src);
        cp_async16(d + (AQ_LO - AQ_HI), gql + src);
    }
    CP_COMMIT();

    auto kv_load = [&](int s) {
        uint32_t dst0 = sb + AKV0 + (uint32_t)(s & 1) * KVBUF;
        int kvb = s * 64;
        #pragma unroll
        for (int i = 0; i < 2; i++) {
            int id = tid + i * 256;
            int r = id >> 3, c = id & 7;
            uint32_t d = dst0 + r * 128 + ((c ^ (r & 7)) << 4);
            size_t src = (size_t)(kvb + r) * 8 + c;
            cp_async16(d,         gkh + src);
            cp_async16(d + 8192,  gkl + src);
            cp_async16(d + 16384, gvh + src);
            cp_async16(d + 24576, gvl + src);
        }
        CP_COMMIT();
    };

    kv_load(0);
    CP_WAIT(1);          // Q complete
    __syncthreads();

    // --- Q fragments (A-frags, 4 k-ticks, hi+lo) ----------------------------
    uint32_t qh[4][4], ql[4][4];
    const int qw = wid * 16;
    #pragma unroll
    for (int kt = 0; kt < 4; kt++) {
        int r = qw + ((lane >> 3) & 1) * 8 + (lane & 7);
        int c = 2 * kt + ((lane >> 4) & 1);
        uint32_t ad = sb + AQ_HI + r * 128 + ((c ^ (r & 7)) << 4);
        ldsm_x4(qh[kt], ad);
        ldsm_x4(ql[kt], ad + (AQ_LO - AQ_HI));
    }

    float o[8][4];
    #pragma unroll
    for (int j = 0; j < 8; j++)
        #pragma unroll
        for (int e = 0; e < 4; e++) o[j][e] = 0.0f;
    float mrow[2] = {-1e30f, -1e30f};
    float lrow[2] = {0.0f, 0.0f};

    for (int s = 0; s < SEQ / 64; s++) {
        if (s + 1 < SEQ / 64) { kv_load(s + 1); CP_WAIT(1); }
        else                  { CP_WAIT(0); }
        __syncthreads();

        const uint32_t kb = sb + AKV0 + (uint32_t)(s & 1) * KVBUF;

        // ---- scores: S = Qhi Khi^T + Qhi Klo^T + Qlo Khi^T ----------------
        float sc[8][4];
        #pragma unroll
        for (int j = 0; j < 8; j++)
            #pragma unroll
            for (int e = 0; e < 4; e++) sc[j][e] = 0.0f;

        #pragma unroll
        for (int kt = 0; kt < 4; kt++) {
            #pragma unroll
            for (int g = 0; g < 4; g++) {
                int r = 16 * g + ((lane >> 4) & 1) * 8 + (lane & 7);
                int c = 2 * kt + ((lane >> 3) & 1);
                uint32_t ad = kb + r * 128 + ((c ^ (r & 7)) << 4);
                uint32_t f[4];
                ldsm_x4(f, ad);                 // Khi
                mma16816(sc[2 * g + 0], qh[kt], f[0], f[1]);
                mma16816(sc[2 * g + 1], qh[kt], f[2], f[3]);
                mma16816(sc[2 * g + 0], ql[kt], f[0], f[1]);
                mma16816(sc[2 * g + 1], ql[kt], f[2], f[3]);
                ldsm_x4(f, ad + 8192);          // Klo
                mma16816(sc[2 * g + 0], qh[kt], f[0], f[1]);
                mma16816(sc[2 * g + 1], qh[kt], f[2], f[3]);
            }
        }

        // ---- online softmax (per half: rows lane/4 and lane/4+8) ----------
        #pragma unroll
        for (int h = 0; h < 2; h++) {
            float mloc = -1e30f;
            #pragma unroll
            for (int j = 0; j < 8; j++)
                mloc = fmaxf(mloc, fmaxf(sc[j][2 * h], sc[j][2 * h + 1]));
            mloc = fmaxf(mloc, __shfl_xor_sync(0xffffffffu, mloc, 1));
            mloc = fmaxf(mloc, __shfl_xor_sync(0xffffffffu, mloc, 2));
            float mnew = fmaxf(mrow[h], mloc);
            float corr = __expf(mrow[h] - mnew);
            float ls = 0.0f;
            #pragma unroll
            for (int j = 0; j < 8; j++) {
                float p0 = __expf(sc[j][2 * h]     - mnew);
                float p1 = __expf(sc[j][2 * h + 1] - mnew);
                sc[j][2 * h] = p0; sc[j][2 * h + 1] = p1;
                ls += p0 + p1;
            }
            ls += __shfl_xor_sync(0xffffffffu, ls, 1);
            ls += __shfl_xor_sync(0xffffffffu, ls, 2);
            lrow[h] = lrow[h] * corr + ls;
            mrow[h] = mnew;
            #pragma unroll
            for (int j = 0; j < 8; j++) {
                o[j][2 * h] *= corr; o[j][2 * h + 1] *= corr;
            }
        }

        // ---- O += Phi Vhi + Phi Vlo + Plo Vhi ------------------------------
        #pragma unroll
        for (int kt = 0; kt < 4; kt++) {
            uint32_t pah[4], pal[4];
            split2(sc[2 * kt][0],     sc[2 * kt][1],     pah[0], pal[0]);
            split2(sc[2 * kt][2],     sc[2 * kt][3],     pah[1], pal[1]);
            split2(sc[2 * kt + 1][0], sc[2 * kt + 1][1], pah[2], pal[2]);
            split2(sc[2 * kt + 1][2], sc[2 * kt + 1][3], pah[3], pal[3]);
            #pragma unroll
            for (int g = 0; g < 4; g++) {
                int r = 16 * kt + ((lane >> 3) & 1) * 8 + (lane & 7);
                int c = 2 * g + ((lane >> 4) & 1);
                uint32_t ad = kb + 16384 + r * 128 + ((c ^ (r & 7)) << 4);
                uint32_t f[4];
                ldsm_x4_t(f, ad);               // Vhi (transposed)
                mma16816(o[2 * g + 0], pah, f[0], f[1]);
                mma16816(o[2 * g + 1], pah, f[2], f[3]);
                mma16816(o[2 * g + 0], pal, f[0], f[1]);
                mma16816(o[2 * g + 1], pal, f[2], f[3]);
                ldsm_x4_t(f, ad + 8192);        // Vlo
                mma16816(o[2 * g + 0], pah, f[0], f[1]);
                mma16816(o[2 * g + 1], pah, f[2], f[3]);
            }
        }
        __syncthreads();
    }

    // ---- epilogue: normalize, split to bf16 hi/lo ctx [M, D] ---------------
    const int b = bh >> 4;
    const int h = bh & 15;
    #pragma unroll
    for (int half = 0; half < 2; half++) {
        float inv = 1.0f / lrow[half];
        int gr = q0 + qw + (lane >> 2) + half * 8;
        size_t rowoff = ((size_t)(b * SEQ + gr)) * D_MODEL + h * DK;
        #pragma unroll
        for (int j = 0; j < 8; j++) {
            float x = o[j][2 * half]     * inv;
            float y = o[j][2 * half + 1] * inv;
            uint32_t ph, pl;
            split2(x, y, ph, pl);
            int col = j * 8 + (lane & 3) * 2;
            *(uint32_t*)&chi_[rowoff + col] = ph;
            *(uint32_t*)&clo_[rowoff + col] = pl;
        }
    }
}

// ---------------------------------------------------------------------------
extern "C" void kernel_launch(void* const* d_in, const int* in_sizes, int n_in,
                              void* d_out, int out_size)
{
    const float* q  = (const float*)d_in[0];
    const float* k  = (const float*)d_in[1];
    const float* v  = (const float*)d_in[2];
    const float* Wq = (const float*)d_in[3];
    const float* bq = (const float*)d_in[4];
    const float* Wk = (const float*)d_in[5];
    const float* bk = (const float*)d_in[6];
    const float* Wv = (const float*)d_in[7];
    const float* bv = (const float*)d_in[8];
    const float* Wo = (const float*)d_in[9];
    const float* bo = (const float*)d_in[10];
    float* out = (float*)d_out;

    __nv_bfloat16 *ahi, *alo, *whi, *wlo;
    __nv_bfloat16 *qhi, *qlo, *khi, *klo, *vhi, *vlo, *chi, *clo;
    cudaGetSymbolAddress((void**)&ahi, g_ahi);
    cudaGetSymbolAddress((void**)&alo, g_alo);
    cudaGetSymbolAddress((void**)&whi, g_whi);
    cudaGetSymbolAddress((void**)&wlo, g_wlo);
    cudaGetSymbolAddress((void**)&qhi, g_qhi);
    cudaGetSymbolAddress((void**)&qlo, g_qlo);
    cudaGetSymbolAddress((void**)&khi, g_khi);
    cudaGetSymbolAddress((void**)&klo, g_klo);
    cudaGetSymbolAddress((void**)&vhi, g_vhi);
    cudaGetSymbolAddress((void**)&vlo, g_vlo);
    cudaGetSymbolAddress((void**)&chi, g_chi);
    cudaGetSymbolAddress((void**)&clo, g_clo);

    const int actN4 = MTOT * D_MODEL / 4;
    const dim3 wtGrid(D_MODEL / 32, D_MODEL / 32);
    const dim3 wtBlk(32, 32);
    const dim3 gemmGrid(D_MODEL / 128, MTOT / 128);
    const size_t gemmSmem = 2 * GSTAGE;

    cudaFuncSetAttribute(gemm_mma, cudaFuncAttributeMaxDynamicSharedMemorySize, (int)gemmSmem);
    cudaFuncSetAttribute(attn_mma, cudaFuncAttributeMaxDynamicSharedMemorySize, ATT_SMEM);

    // Q projection (scale folded: 1/sqrt(64) = 0.125)
    conv_wt<<<wtGrid, wtBlk>>>(Wq, whi, wlo);
    conv_split<<<(actN4 + 255) / 256, 256>>>((const float4*)q, ahi, alo, actN4);
    gemm_mma<<<gemmGrid, 256, gemmSmem>>>(ahi, alo, whi, wlo, bq, nullptr, qhi, qlo, 0.125f);
    // K projection
    conv_wt<<<wtGrid, wtBlk>>>(Wk, whi, wlo);
    conv_split<<<(actN4 + 255) / 256, 256>>>((const float4*)k, ahi, alo, actN4);
    gemm_mma<<<gemmGrid, 256, gemmSmem>>>(ahi, alo, whi, wlo, bk, nullptr, khi, klo, 1.0f);
    // V projection
    conv_wt<<<wtGrid, wtBlk>>>(Wv, whi, wlo);
    conv_split<<<(actN4 + 255) / 256, 256>>>((const float4*)v, ahi, alo, actN4);
    gemm_mma<<<gemmGrid, 256, gemmSmem>>>(ahi, alo, whi, wlo, bv, nullptr, vhi, vlo, 1.0f);

    // Attention (tensor cores) — writes ctx as bf16 hi/lo directly
    attn_mma<<<dim3(SEQ / 128, BATCH * NHEADS), 256, ATT_SMEM>>>(
        qhi, qlo, khi, klo, vhi, vlo, chi, clo);

    // Output projection (fp32 out)
    conv_wt<<<wtGrid, wtBlk>>>(Wo, whi, wlo);
    gemm_mma<<<gemmGrid, 256, gemmSmem>>>(chi, clo, whi, wlo, bo, out, nullptr, nullptr, 1.0f);
}

// round 5
// speedup vs baseline: 2.7703x; 1.1249x over previous
#include <cuda_runtime.h>
#include <cuda_bf16.h>
#include <cstdint>

#define D_MODEL 1024
#define NHEADS  16
#define DK      64
#define BATCH   2
#define SEQ     2048
#define MTOT    (BATCH * SEQ)   // 4096

#define ACT_SLAB ((size_t)MTOT * D_MODEL)      // 4M elements
#define W_SLAB   ((size_t)D_MODEL * D_MODEL)   // 1M elements

// ---------------------------------------------------------------------------
// Scratch (device globals — no allocation allowed)
// ---------------------------------------------------------------------------
__device__ __nv_bfloat16 g_ahi[3 * ACT_SLAB];  // activation splits (q,k,v)
__device__ __nv_bfloat16 g_alo[3 * ACT_SLAB];
__device__ __nv_bfloat16 g_whi[4 * W_SLAB];    // W^T splits (Wq,Wk,Wv,Wo) [N,K]
__device__ __nv_bfloat16 g_wlo[4 * W_SLAB];

__device__ __nv_bfloat16 g_phi[3 * ACT_SLAB];  // projected q/k/v hi [B,H,S,DK]
__device__ __nv_bfloat16 g_plo[3 * ACT_SLAB];
__device__ __nv_bfloat16 g_chi[ACT_SLAB];      // ctx split [M, D]
__device__ __nv_bfloat16 g_clo[ACT_SLAB];

// ---------------------------------------------------------------------------
// helpers
// ---------------------------------------------------------------------------
__device__ __forceinline__ uint32_t smem_to_u32(const void* p) {
    uint32_t a;
    asm("{ .reg .u64 t; cvta.to.shared.u64 t, %1; cvt.u32.u64 %0, t; }"
        : "=r"(a) : "l"(p));
    return a;
}
__device__ __forceinline__ void cp_async16(uint32_t dst, const void* src) {
    asm volatile("cp.async.cg.shared.global [%0], [%1], 16;"
                 :: "r"(dst), "l"(src) : "memory");
}
#define CP_COMMIT() asm volatile("cp.async.commit_group;" ::: "memory")
#define CP_WAIT(n)  asm volatile("cp.async.wait_group %0;" :: "n"(n) : "memory")

__device__ __forceinline__ void ldsm_x4(uint32_t* d, uint32_t addr) {
    asm volatile("ldmatrix.sync.aligned.m8n8.x4.shared.b16 {%0,%1,%2,%3}, [%4];"
                 : "=r"(d[0]), "=r"(d[1]), "=r"(d[2]), "=r"(d[3]) : "r"(addr));
}
__device__ __forceinline__ void ldsm_x4_t(uint32_t* d, uint32_t addr) {
    asm volatile("ldmatrix.sync.aligned.m8n8.x4.trans.shared.b16 {%0,%1,%2,%3}, [%4];"
                 : "=r"(d[0]), "=r"(d[1]), "=r"(d[2]), "=r"(d[3]) : "r"(addr));
}
__device__ __forceinline__ void mma16816(float* c, const uint32_t* a,
                                         uint32_t b0, uint32_t b1) {
    asm volatile(
        "mma.sync.aligned.m16n8k16.row.col.f32.bf16.bf16.f32 "
        "{%0,%1,%2,%3}, {%4,%5,%6,%7}, {%8,%9}, {%0,%1,%2,%3};"
        : "+f"(c[0]), "+f"(c[1]), "+f"(c[2]), "+f"(c[3])
        : "r"(a[0]), "r"(a[1]), "r"(a[2]), "r"(a[3]), "r"(b0), "r"(b1));
}
__device__ __forceinline__ void split2(float x, float y, uint32_t& hi, uint32_t& lo) {
    __nv_bfloat16 hx = __float2bfloat16(x);
    __nv_bfloat16 hy = __float2bfloat16(y);
    __nv_bfloat16 lx = __float2bfloat16(x - __bfloat162float(hx));
    __nv_bfloat16 ly = __float2bfloat16(y - __bfloat162float(hy));
    hi = ((uint32_t)*(unsigned short*)&hy << 16) | (uint32_t)*(unsigned short*)&hx;
    lo = ((uint32_t)*(unsigned short*)&ly << 16) | (uint32_t)*(unsigned short*)&lx;
}

// ---------------------------------------------------------------------------
// fp32 -> bf16 hi/lo split, all 3 activations in one launch (z = input idx)
// ---------------------------------------------------------------------------
__global__ __launch_bounds__(256) void conv_split_all(
    const float4* __restrict__ x0, const float4* __restrict__ x1,
    const float4* __restrict__ x2,
    __nv_bfloat16* __restrict__ hi, __nv_bfloat16* __restrict__ lo)
{
    const int z = blockIdx.y;
    const float4* x = z == 0 ? x0 : (z == 1 ? x1 : x2);
    int i = blockIdx.x * 256 + threadIdx.x;
    float4 v = x[i];
    __nv_bfloat16 h[4], l[4];
    float f[4] = {v.x, v.y, v.z, v.w};
    #pragma unroll
    for (int e = 0; e < 4; e++) {
        h[e] = __float2bfloat16(f[e]);
        l[e] = __float2bfloat16(f[e] - __bfloat162float(h[e]));
    }
    size_t off = (size_t)z * ACT_SLAB + (size_t)i * 4;
    *(uint2*)&hi[off] = *(uint2*)h;
    *(uint2*)&lo[off] = *(uint2*)l;
}

// All 4 weights: W [K,N] fp32 -> W^T [N,K] bf16 hi/lo (z = weight idx)
__global__ __launch_bounds__(1024) void conv_wt_all(
    const float* __restrict__ W0, const float* __restrict__ W1,
    const float* __restrict__ W2, const float* __restrict__ W3,
    __nv_bfloat16* __restrict__ hi, __nv_bfloat16* __restrict__ lo)
{
    __shared__ float t[32][33];
    const int z = blockIdx.z;
    const float* W = z == 0 ? W0 : (z == 1 ? W1 : (z == 2 ? W2 : W3));
    int tx = threadIdx.x, ty = threadIdx.y;
    int n0 = blockIdx.x * 32, k0 = blockIdx.y * 32;
    t[ty][tx] = W[(size_t)(k0 + ty) * D_MODEL + n0 + tx];
    __syncthreads();
    float v = t[tx][ty];
    __nv_bfloat16 h = __float2bfloat16(v);
    size_t o = (size_t)z * W_SLAB + (size_t)(n0 + ty) * D_MODEL + k0 + tx;
    hi[o] = h;
    lo[o] = __float2bfloat16(v - __bfloat162float(h));
}

// ---------------------------------------------------------------------------
// bf16x3 tensor-core GEMM (batched over blockIdx.z).
// out_z = (ahi+alo)_z [M,K] @ (whi+wlo)_z [N,K]^T + bias_z
// If ohi != 0: write bf16 hi/lo, head-split [B,H,S,DK] into slab z, scaled.
// Else (grid.z==1): fp32 row-major to outp.
// ---------------------------------------------------------------------------
#define GSTAGE 40960
#define OFF_AHI 0
#define OFF_ALO 10240
#define OFF_BHI 20480
#define OFF_BLO 30720
#define NSTAGES 32

__global__ __launch_bounds__(256) void gemm_mma(
    const __nv_bfloat16* __restrict__ a_hi, const __nv_bfloat16* __restrict__ a_lo,
    const __nv_bfloat16* __restrict__ w_hi, const __nv_bfloat16* __restrict__ w_lo,
    const float* __restrict__ b0, const float* __restrict__ b1,
    const float* __restrict__ b2,
    float* __restrict__ outp,
    __nv_bfloat16* __restrict__ ohi, __nv_bfloat16* __restrict__ olo,
    float scale0)
{
    extern __shared__ char smem[];
    const uint32_t sbase = smem_to_u32(smem);
    const int tid  = threadIdx.x;
    const int wid  = tid >> 5;
    const int lane = tid & 31;
    const int wm = wid >> 1;
    const int wn = wid & 1;
    const int m0 = blockIdx.y * 128;
    const int n0 = blockIdx.x * 128;
    const int z  = blockIdx.z;
    const float* bias = z == 0 ? b0 : (z == 1 ? b1 : b2);
    const float scale = z == 0 ? scale0 : 1.0f;

    const uint4* gAhi = (const uint4*)(a_hi + (size_t)z * ACT_SLAB);
    const uint4* gAlo = (const uint4*)(a_lo + (size_t)z * ACT_SLAB);
    const uint4* gBhi = (const uint4*)(w_hi + (size_t)z * W_SLAB);
    const uint4* gBlo = (const uint4*)(w_lo + (size_t)z * W_SLAB);

    auto load_stage = [&](int s) {
        const uint32_t stb = sbase + (uint32_t)(s & 1) * GSTAGE;
        const int koff4 = s * 4;
        #pragma unroll
        for (int t = 0; t < 2; t++) {
            int id = tid + (t << 8);
            int row = id >> 2;
            int c   = id & 3;
            uint32_t d = stb + row * 80 + c * 16;
            size_t srcA = (size_t)(m0 + row) * 128 + koff4 + c;
            size_t srcB = (size_t)(n0 + row) * 128 + koff4 + c;
            cp_async16(d + OFF_AHI, gAhi + srcA);
            cp_async16(d + OFF_ALO, gAlo + srcA);
            cp_async16(d + OFF_BHI, gBhi + srcB);
            cp_async16(d + OFF_BLO, gBlo + srcB);
        }
        CP_COMMIT();
    };

    float acc[2][8][4];
    #pragma unroll
    for (int i = 0; i < 2; i++)
        #pragma unroll
        for (int j = 0; j < 8; j++)
            #pragma unroll
            for (int e = 0; e < 4; e++) acc[i][j][e] = 0.0f;

    const int lj = lane >> 3;
    const int lr = lane & 7;

    load_stage(0);

    for (int s = 0; s < NSTAGES; s++) {
        if (s + 1 < NSTAGES) load_stage(s + 1);
        if (s + 1 < NSTAGES) { CP_WAIT(1); } else { CP_WAIT(0); }
        __syncthreads();

        const uint32_t stb = sbase + (uint32_t)(s & 1) * GSTAGE;

        #pragma unroll
        for (int t = 0; t < 2; t++) {
            const int kb = t * 16;
            uint32_t bhi[4][4], blo[4][4];
            #pragma unroll
            for (int g = 0; g < 4; g++) {
                int brow = wn * 64 + g * 16 + ((lj >> 1) << 3) + lr;
                int bcol = kb + ((lj & 1) << 3);
                uint32_t ba = stb + brow * 80 + bcol * 2;
                ldsm_x4(bhi[g], ba + OFF_BHI);
                ldsm_x4(blo[g], ba + OFF_BLO);
            }
            uint32_t a[2][4];
            {
                int acol = kb + ((lj >> 1) << 3);
                #pragma unroll
                for (int fm = 0; fm < 2; fm++) {
                    int arow = wm * 32 + fm * 16 + ((lj & 1) << 3) + lr;
                    ldsm_x4(a[fm], stb + OFF_AHI + arow * 80 + acol * 2);
                }
            }
            #pragma unroll
            for (int fm = 0; fm < 2; fm++)
                #pragma unroll
                for (int g = 0; g < 4; g++) {
                    mma16816(acc[fm][g * 2 + 0], a[fm], bhi[g][0], bhi[g][1]);
                    mma16816(acc[fm][g * 2 + 1], a[fm], bhi[g][2], bhi[g][3]);
                    mma16816(acc[fm][g * 2 + 0], a[fm], blo[g][0], blo[g][1]);
                    mma16816(acc[fm][g * 2 + 1], a[fm], blo[g][2], blo[g][3]);
                }
            {
                int acol = kb + ((lj >> 1) << 3);
                #pragma unroll
                for (int fm = 0; fm < 2; fm++) {
                    int arow = wm * 32 + fm * 16 + ((lj & 1) << 3) + lr;
                    ldsm_x4(a[fm], stb + OFF_ALO + arow * 80 + acol * 2);
                }
            }
            #pragma unroll
            for (int fm = 0; fm < 2; fm++)
                #pragma unroll
                for (int g = 0; g < 4; g++) {
                    mma16816(acc[fm][g * 2 + 0], a[fm], bhi[g][0], bhi[g][1]);
                    mma16816(acc[fm][g * 2 + 1], a[fm], bhi[g][2], bhi[g][3]);
                }
        }
        __syncthreads();
    }

    // ---- epilogue --------------------------------------------------------
    const int qrow = lane >> 2;
    const int qcol = (lane & 3) * 2;
    #pragma unroll
    for (int fm = 0; fm < 2; fm++) {
        #pragma unroll
        for (int fn = 0; fn < 8; fn++) {
            int col = n0 + wn * 64 + fn * 8 + qcol;
            float2 bv = *(const float2*)&bias[col];
            #pragma unroll
            for (int half = 0; half < 2; half++) {
                int gm = m0 + wm * 32 + fm * 16 + qrow + half * 8;
                float x = (acc[fm][fn][half * 2 + 0] + bv.x) * scale;
                float y = (acc[fm][fn][half * 2 + 1] + bv.y) * scale;
                if (ohi) {
                    int b = gm >> 11, ss = gm & 2047;
                    int h = col >> 6, d = col & 63;
                    size_t off = (size_t)z * ACT_SLAB +
                                 (((size_t)(b * NHEADS + h)) * SEQ + ss) * DK + d;
                    uint32_t ph, pl;
                    split2(x, y, ph, pl);
                    *(uint32_t*)&ohi[off] = ph;
                    *(uint32_t*)&olo[off] = pl;
                } else {
                    *(float2*)&outp[(size_t)gm * D_MODEL + col] = make_float2(x, y);
                }
            }
        }
    }
}

// ---------------------------------------------------------------------------
// Tensor-core flash attention, bf16x3. CTA: 128 q rows, 8 warps.
// KV tiles of 128 keys, double-buffered.
// SMEM: Qhi 16K | Qlo 16K | 2 x (Khi 16K | Klo 16K | Vhi 16K | Vlo 16K)
// ---------------------------------------------------------------------------
#define AQ_HI 0
#define AQ_LO 16384
#define AKV0  32768
#define KVBUF 65536
#define ATT_SMEM (AKV0 + 2 * KVBUF)   // 163840

__global__ __launch_bounds__(256) void attn_mma(
    const __nv_bfloat16* __restrict__ phi_, const __nv_bfloat16* __restrict__ plo_,
    __nv_bfloat16* __restrict__ chi_, __nv_bfloat16* __restrict__ clo_)
{
    extern __shared__ char smem[];
    const uint32_t sb = smem_to_u32(smem);
    const int tid = threadIdx.x, wid = tid >> 5, lane = tid & 31;
    const int bh = blockIdx.y;
    const int q0 = blockIdx.x * 128;
    const size_t base = (size_t)bh * SEQ * DK;

    const uint4* gqh = (const uint4*)(phi_ + base);                 // z=0 slab
    const uint4* gql = (const uint4*)(plo_ + base);
    const uint4* gkh = (const uint4*)(phi_ + ACT_SLAB + base);      // z=1 slab
    const uint4* gkl = (const uint4*)(plo_ + ACT_SLAB + base);
    const uint4* gvh = (const uint4*)(phi_ + 2 * ACT_SLAB + base);  // z=2 slab
    const uint4* gvl = (const uint4*)(plo_ + 2 * ACT_SLAB + base);

    // --- prologue: Q tile (128 rows x 8 chunks, swizzled) -------------------
    #pragma unroll
    for (int i = 0; i < 4; i++) {
        int id = tid + i * 256;
        int r = id >> 3, c = id & 7;
        uint32_t d = sb + AQ_HI + r * 128 + ((c ^ (r & 7)) << 4);
        size_t src = (size_t)(q0 + r) * 8 + c;
        cp_async16(d, gqh + src);
        cp_async16(d + (AQ_LO - AQ_HI), gql + src);
    }
    CP_COMMIT();

    auto kv_load = [&](int s) {
        uint32_t dst0 = sb + AKV0 + (uint32_t)(s & 1) * KVBUF;
        int kvb = s * 128;
        #pragma unroll
        for (int i = 0; i < 4; i++) {
            int id = tid + i * 256;
            int r = id >> 3, c = id & 7;
            uint32_t d = dst0 + r * 128 + ((c ^ (r & 7)) << 4);
            size_t src = (size_t)(kvb + r) * 8 + c;
            cp_async16(d,         gkh + src);
            cp_async16(d + 16384, gkl + src);
            cp_async16(d + 32768, gvh + src);
            cp_async16(d + 49152, gvl + src);
        }
        CP_COMMIT();
    };

    kv_load(0);
    CP_WAIT(1);          // Q complete
    __syncthreads();

    // --- Q fragments (A-frags, 4 k-ticks, hi+lo) ----------------------------
    uint32_t qh[4][4], ql[4][4];
    const int qw = wid * 16;
    #pragma unroll
    for (int kt = 0; kt < 4; kt++) {
        int r = qw + ((lane >> 3) & 1) * 8 + (lane & 7);
        int c = 2 * kt + ((lane >> 4) & 1);
        uint32_t ad = sb + AQ_HI + r * 128 + ((c ^ (r & 7)) << 4);
        ldsm_x4(qh[kt], ad);
        ldsm_x4(ql[kt], ad + (AQ_LO - AQ_HI));
    }

    float o[8][4];
    #pragma unroll
    for (int j = 0; j < 8; j++)
        #pragma unroll
        for (int e = 0; e < 4; e++) o[j][e] = 0.0f;
    float mrow[2] = {-1e30f, -1e30f};
    float lrow[2] = {0.0f, 0.0f};

    const int NITER = SEQ / 128;   // 16
    for (int s = 0; s < NITER; s++) {
        if (s + 1 < NITER) { kv_load(s + 1); CP_WAIT(1); }
        else               { CP_WAIT(0); }
        __syncthreads();

        const uint32_t kb = sb + AKV0 + (uint32_t)(s & 1) * KVBUF;

        // ---- scores: S[16 x 128] = Qhi Khi^T + Qhi Klo^T + Qlo Khi^T ------
        float sc[16][4];
        #pragma unroll
        for (int j = 0; j < 16; j++)
            #pragma unroll
            for (int e = 0; e < 4; e++) sc[j][e] = 0.0f;

        #pragma unroll
        for (int kt = 0; kt < 4; kt++) {
            #pragma unroll
            for (int g = 0; g < 8; g++) {
                int r = 16 * g + ((lane >> 4) & 1) * 8 + (lane & 7);
                int c = 2 * kt + ((lane >> 3) & 1);
                uint32_t ad = kb + r * 128 + ((c ^ (r & 7)) << 4);
                uint32_t f[4];
                ldsm_x4(f, ad);                 // Khi
                mma16816(sc[2 * g + 0], qh[kt], f[0], f[1]);
                mma16816(sc[2 * g + 1], qh[kt], f[2], f[3]);
                mma16816(sc[2 * g + 0], ql[kt], f[0], f[1]);
                mma16816(sc[2 * g + 1], ql[kt], f[2], f[3]);
                ldsm_x4(f, ad + 16384);         // Klo
                mma16816(sc[2 * g + 0], qh[kt], f[0], f[1]);
                mma16816(sc[2 * g + 1], qh[kt], f[2], f[3]);
            }
        }

        // ---- online softmax ------------------------------------------------
        #pragma unroll
        for (int h = 0; h < 2; h++) {
            float mloc = -1e30f;
            #pragma unroll
            for (int j = 0; j < 16; j++)
                mloc = fmaxf(mloc, fmaxf(sc[j][2 * h], sc[j][2 * h + 1]));
            mloc = fmaxf(mloc, __shfl_xor_sync(0xffffffffu, mloc, 1));
            mloc = fmaxf(mloc, __shfl_xor_sync(0xffffffffu, mloc, 2));
            float mnew = fmaxf(mrow[h], mloc);
            float corr = __expf(mrow[h] - mnew);
            float ls = 0.0f;
            #pragma unroll
            for (int j = 0; j < 16; j++) {
                float p0 = __expf(sc[j][2 * h]     - mnew);
                float p1 = __expf(sc[j][2 * h + 1] - mnew);
                sc[j][2 * h] = p0; sc[j][2 * h + 1] = p1;
                ls += p0 + p1;
            }
            ls += __shfl_xor_sync(0xffffffffu, ls, 1);
            ls += __shfl_xor_sync(0xffffffffu, ls, 2);
            lrow[h] = lrow[h] * corr + ls;
            mrow[h] = mnew;
            #pragma unroll
            for (int j = 0; j < 8; j++) {
                o[j][2 * h] *= corr; o[j][2 * h + 1] *= corr;
            }
        }

        // ---- O += Phi Vhi + Phi Vlo + Plo Vhi (k over 128 keys) ------------
        #pragma unroll
        for (int kt = 0; kt < 8; kt++) {
            uint32_t pah[4], pal[4];
            split2(sc[2 * kt][0],     sc[2 * kt][1],     pah[0], pal[0]);
            split2(sc[2 * kt][2],     sc[2 * kt][3],     pah[1], pal[1]);
            split2(sc[2 * kt + 1][0], sc[2 * kt + 1][1], pah[2], pal[2]);
            split2(sc[2 * kt + 1][2], sc[2 * kt + 1][3], pah[3], pal[3]);
            #pragma unroll
            for (int g = 0; g < 4; g++) {
                int r = 16 * kt + ((lane >> 3) & 1) * 8 + (lane & 7);
                int c = 2 * g + ((lane >> 4) & 1);
                uint32_t ad = kb + 32768 + r * 128 + ((c ^ (r & 7)) << 4);
                uint32_t f[4];
                ldsm_x4_t(f, ad);               // Vhi (transposed)
                mma16816(o[2 * g + 0], pah, f[0], f[1]);
                mma16816(o[2 * g + 1], pah, f[2], f[3]);
                mma16816(o[2 * g + 0], pal, f[0], f[1]);
                mma16816(o[2 * g + 1], pal, f[2], f[3]);
                ldsm_x4_t(f, ad + 16384);       // Vlo
                mma16816(o[2 * g + 0], pah, f[0], f[1]);
                mma16816(o[2 * g + 1], pah, f[2], f[3]);
            }
        }
        __syncthreads();
    }

    // ---- epilogue: normalize, split to bf16 hi/lo ctx [M, D] ---------------
    const int b = bh >> 4;
    const int h = bh & 15;
    #pragma unroll
    for (int half = 0; half < 2; half++) {
        float inv = 1.0f / lrow[half];
        int gr = q0 + qw + (lane >> 2) + half * 8;
        size_t rowoff = ((size_t)(b * SEQ + gr)) * D_MODEL + h * DK;
        #pragma unroll
        for (int j = 0; j < 8; j++) {
            float x = o[j][2 * half]     * inv;
            float y = o[j][2 * half + 1] * inv;
            uint32_t ph, pl;
            split2(x, y, ph, pl);
            int col = j * 8 + (lane & 3) * 2;
            *(uint32_t*)&chi_[rowoff + col] = ph;
            *(uint32_t*)&clo_[rowoff + col] = pl;
        }
    }
}

// ---------------------------------------------------------------------------
extern "C" void kernel_launch(void* const* d_in, const int* in_sizes, int n_in,
                              void* d_out, int out_size)
{
    const float* q  = (const float*)d_in[0];
    const float* k  = (const float*)d_in[1];
    const float* v  = (const float*)d_in[2];
    const float* Wq = (const float*)d_in[3];
    const float* bq = (const float*)d_in[4];
    const float* Wk = (const float*)d_in[5];
    const float* bk = (const float*)d_in[6];
    const float* Wv = (const float*)d_in[7];
    const float* bv = (const float*)d_in[8];
    const float* Wo = (const float*)d_in[9];
    const float* bo = (const float*)d_in[10];
    float* out = (float*)d_out;

    __nv_bfloat16 *ahi, *alo, *whi, *wlo, *phi, *plo, *chi, *clo;
    cudaGetSymbolAddress((void**)&ahi, g_ahi);
    cudaGetSymbolAddress((void**)&alo, g_alo);
    cudaGetSymbolAddress((void**)&whi, g_whi);
    cudaGetSymbolAddress((void**)&wlo, g_wlo);
    cudaGetSymbolAddress((void**)&phi, g_phi);
    cudaGetSymbolAddress((void**)&plo, g_plo);
    cudaGetSymbolAddress((void**)&chi, g_chi);
    cudaGetSymbolAddress((void**)&clo, g_clo);

    const int actN4 = MTOT * D_MODEL / 4;   // 1M float4 per input
    const size_t gemmSmem = 2 * GSTAGE;

    cudaFuncSetAttribute(gemm_mma, cudaFuncAttributeMaxDynamicSharedMemorySize, (int)gemmSmem);
    cudaFuncSetAttribute(attn_mma, cudaFuncAttributeMaxDynamicSharedMemorySize, ATT_SMEM);

    // 1) Convert all weights (W^T hi/lo) and all activations (hi/lo)
    conv_wt_all<<<dim3(D_MODEL / 32, D_MODEL / 32, 4), dim3(32, 32)>>>(
        Wq, Wk, Wv, Wo, whi, wlo);
    conv_split_all<<<dim3(actN4 / 256, 3), 256>>>(
        (const float4*)q, (const float4*)k, (const float4*)v, ahi, alo);

    // 2) Q/K/V projections in one batched launch (z = 0,1,2).
    //    Q output pre-scaled by 1/sqrt(DK) = 0.125.
    gemm_mma<<<dim3(D_MODEL / 128, MTOT / 128, 3), 256, gemmSmem>>>(
        ahi, alo, whi, wlo, bq, bk, bv, nullptr, phi, plo, 0.125f);

    // 3) Attention (tensor cores) — ctx written as bf16 hi/lo
    attn_mma<<<dim3(SEQ / 128, BATCH * NHEADS), 256, ATT_SMEM>>>(phi, plo, chi, clo);

    // 4) Output projection (fp32 out). Wo slab = index 3.
    gemm_mma<<<dim3(D_MODEL / 128, MTOT / 128, 1), 256, gemmSmem>>>(
        chi, clo, whi + 3 * W_SLAB, wlo + 3 * W_SLAB,
        bo, bo, bo, out, nullptr, nullptr, 1.0f);
}

// round 6
// speedup vs baseline: 2.8891x; 1.0429x over previous
#include <cuda_runtime.h>
#include <cuda_bf16.h>
#include <cstdint>

#define D_MODEL 1024
#define NHEADS  16
#define DK      64
#define BATCH   2
#define SEQ     2048
#define MTOT    (BATCH * SEQ)   // 4096

#define ACT_SLAB ((size_t)MTOT * D_MODEL)      // 4M elements
#define W_SLAB   ((size_t)D_MODEL * D_MODEL)   // 1M elements

// ---------------------------------------------------------------------------
// Scratch (device globals — no allocation allowed)
// ---------------------------------------------------------------------------
__device__ __nv_bfloat16 g_ahi[3 * ACT_SLAB];  // activation splits (q,k,v)
__device__ __nv_bfloat16 g_alo[3 * ACT_SLAB];
__device__ __nv_bfloat16 g_whi[4 * W_SLAB];    // W^T splits (Wq,Wk,Wv,Wo) [N,K]
__device__ __nv_bfloat16 g_wlo[4 * W_SLAB];

__device__ __nv_bfloat16 g_phi[3 * ACT_SLAB];  // projected q/k/v hi [B,H,S,DK]
__device__ __nv_bfloat16 g_plo[3 * ACT_SLAB];
__device__ __nv_bfloat16 g_chi[ACT_SLAB];      // ctx split [M, D]
__device__ __nv_bfloat16 g_clo[ACT_SLAB];

// ---------------------------------------------------------------------------
// helpers
// ---------------------------------------------------------------------------
__device__ __forceinline__ uint32_t smem_to_u32(const void* p) {
    uint32_t a;
    asm("{ .reg .u64 t; cvta.to.shared.u64 t, %1; cvt.u32.u64 %0, t; }"
        : "=r"(a) : "l"(p));
    return a;
}
__device__ __forceinline__ void cp_async16(uint32_t dst, const void* src) {
    asm volatile("cp.async.cg.shared.global [%0], [%1], 16;"
                 :: "r"(dst), "l"(src) : "memory");
}
#define CP_COMMIT() asm volatile("cp.async.commit_group;" ::: "memory")
#define CP_WAIT(n)  asm volatile("cp.async.wait_group %0;" :: "n"(n) : "memory")

__device__ __forceinline__ void ldsm_x4(uint32_t* d, uint32_t addr) {
    asm volatile("ldmatrix.sync.aligned.m8n8.x4.shared.b16 {%0,%1,%2,%3}, [%4];"
                 : "=r"(d[0]), "=r"(d[1]), "=r"(d[2]), "=r"(d[3]) : "r"(addr));
}
__device__ __forceinline__ void ldsm_x4_t(uint32_t* d, uint32_t addr) {
    asm volatile("ldmatrix.sync.aligned.m8n8.x4.trans.shared.b16 {%0,%1,%2,%3}, [%4];"
                 : "=r"(d[0]), "=r"(d[1]), "=r"(d[2]), "=r"(d[3]) : "r"(addr));
}
__device__ __forceinline__ void mma16816(float* c, const uint32_t* a,
                                         uint32_t b0, uint32_t b1) {
    asm volatile(
        "mma.sync.aligned.m16n8k16.row.col.f32.bf16.bf16.f32 "
        "{%0,%1,%2,%3}, {%4,%5,%6,%7}, {%8,%9}, {%0,%1,%2,%3};"
        : "+f"(c[0]), "+f"(c[1]), "+f"(c[2]), "+f"(c[3])
        : "r"(a[0]), "r"(a[1]), "r"(a[2]), "r"(a[3]), "r"(b0), "r"(b1));
}
__device__ __forceinline__ void split2(float x, float y, uint32_t& hi, uint32_t& lo) {
    __nv_bfloat16 hx = __float2bfloat16(x);
    __nv_bfloat16 hy = __float2bfloat16(y);
    __nv_bfloat16 lx = __float2bfloat16(x - __bfloat162float(hx));
    __nv_bfloat16 ly = __float2bfloat16(y - __bfloat162float(hy));
    hi = ((uint32_t)*(unsigned short*)&hy << 16) | (uint32_t)*(unsigned short*)&hx;
    lo = ((uint32_t)*(unsigned short*)&ly << 16) | (uint32_t)*(unsigned short*)&lx;
}
__device__ __forceinline__ float ex2(float x) {
    float y;
    asm("ex2.approx.ftz.f32 %0, %1;" : "=f"(y) : "f"(x));
    return y;
}

// ---------------------------------------------------------------------------
// fp32 -> bf16 hi/lo split, all 3 activations in one launch (y = input idx)
// ---------------------------------------------------------------------------
__global__ __launch_bounds__(256) void conv_split_all(
    const float4* __restrict__ x0, const float4* __restrict__ x1,
    const float4* __restrict__ x2,
    __nv_bfloat16* __restrict__ hi, __nv_bfloat16* __restrict__ lo)
{
    const int z = blockIdx.y;
    const float4* x = z == 0 ? x0 : (z == 1 ? x1 : x2);
    int i = blockIdx.x * 256 + threadIdx.x;
    float4 v = x[i];
    __nv_bfloat16 h[4], l[4];
    float f[4] = {v.x, v.y, v.z, v.w};
    #pragma unroll
    for (int e = 0; e < 4; e++) {
        h[e] = __float2bfloat16(f[e]);
        l[e] = __float2bfloat16(f[e] - __bfloat162float(h[e]));
    }
    size_t off = (size_t)z * ACT_SLAB + (size_t)i * 4;
    *(uint2*)&hi[off] = *(uint2*)h;
    *(uint2*)&lo[off] = *(uint2*)l;
}

// All 4 weights: W [K,N] fp32 -> W^T [N,K] bf16 hi/lo (z = weight idx)
__global__ __launch_bounds__(1024) void conv_wt_all(
    const float* __restrict__ W0, const float* __restrict__ W1,
    const float* __restrict__ W2, const float* __restrict__ W3,
    __nv_bfloat16* __restrict__ hi, __nv_bfloat16* __restrict__ lo)
{
    __shared__ float t[32][33];
    const int z = blockIdx.z;
    const float* W = z == 0 ? W0 : (z == 1 ? W1 : (z == 2 ? W2 : W3));
    int tx = threadIdx.x, ty = threadIdx.y;
    int n0 = blockIdx.x * 32, k0 = blockIdx.y * 32;
    t[ty][tx] = W[(size_t)(k0 + ty) * D_MODEL + n0 + tx];
    __syncthreads();
    float v = t[tx][ty];
    __nv_bfloat16 h = __float2bfloat16(v);
    size_t o = (size_t)z * W_SLAB + (size_t)(n0 + ty) * D_MODEL + k0 + tx;
    hi[o] = h;
    lo[o] = __float2bfloat16(v - __bfloat162float(h));
}

// ---------------------------------------------------------------------------
// bf16x3 tensor-core GEMM (batched over blockIdx.z). Unchanged from R5.
// ---------------------------------------------------------------------------
#define GSTAGE 40960
#define OFF_AHI 0
#define OFF_ALO 10240
#define OFF_BHI 20480
#define OFF_BLO 30720
#define NSTAGES 32

__global__ __launch_bounds__(256) void gemm_mma(
    const __nv_bfloat16* __restrict__ a_hi, const __nv_bfloat16* __restrict__ a_lo,
    const __nv_bfloat16* __restrict__ w_hi, const __nv_bfloat16* __restrict__ w_lo,
    const float* __restrict__ b0, const float* __restrict__ b1,
    const float* __restrict__ b2,
    float* __restrict__ outp,
    __nv_bfloat16* __restrict__ ohi, __nv_bfloat16* __restrict__ olo,
    float scale0)
{
    extern __shared__ char smem[];
    const uint32_t sbase = smem_to_u32(smem);
    const int tid  = threadIdx.x;
    const int wid  = tid >> 5;
    const int lane = tid & 31;
    const int wm = wid >> 1;
    const int wn = wid & 1;
    const int m0 = blockIdx.y * 128;
    const int n0 = blockIdx.x * 128;
    const int z  = blockIdx.z;
    const float* bias = z == 0 ? b0 : (z == 1 ? b1 : b2);
    const float scale = z == 0 ? scale0 : 1.0f;

    const uint4* gAhi = (const uint4*)(a_hi + (size_t)z * ACT_SLAB);
    const uint4* gAlo = (const uint4*)(a_lo + (size_t)z * ACT_SLAB);
    const uint4* gBhi = (const uint4*)(w_hi + (size_t)z * W_SLAB);
    const uint4* gBlo = (const uint4*)(w_lo + (size_t)z * W_SLAB);

    auto load_stage = [&](int s) {
        const uint32_t stb = sbase + (uint32_t)(s & 1) * GSTAGE;
        const int koff4 = s * 4;
        #pragma unroll
        for (int t = 0; t < 2; t++) {
            int id = tid + (t << 8);
            int row = id >> 2;
            int c   = id & 3;
            uint32_t d = stb + row * 80 + c * 16;
            size_t srcA = (size_t)(m0 + row) * 128 + koff4 + c;
            size_t srcB = (size_t)(n0 + row) * 128 + koff4 + c;
            cp_async16(d + OFF_AHI, gAhi + srcA);
            cp_async16(d + OFF_ALO, gAlo + srcA);
            cp_async16(d + OFF_BHI, gBhi + srcB);
            cp_async16(d + OFF_BLO, gBlo + srcB);
        }
        CP_COMMIT();
    };

    float acc[2][8][4];
    #pragma unroll
    for (int i = 0; i < 2; i++)
        #pragma unroll
        for (int j = 0; j < 8; j++)
            #pragma unroll
            for (int e = 0; e < 4; e++) acc[i][j][e] = 0.0f;

    const int lj = lane >> 3;
    const int lr = lane & 7;

    load_stage(0);

    for (int s = 0; s < NSTAGES; s++) {
        if (s + 1 < NSTAGES) load_stage(s + 1);
        if (s + 1 < NSTAGES) { CP_WAIT(1); } else { CP_WAIT(0); }
        __syncthreads();

        const uint32_t stb = sbase + (uint32_t)(s & 1) * GSTAGE;

        #pragma unroll
        for (int t = 0; t < 2; t++) {
            const int kb = t * 16;
            uint32_t bhi[4][4], blo[4][4];
            #pragma unroll
            for (int g = 0; g < 4; g++) {
                int brow = wn * 64 + g * 16 + ((lj >> 1) << 3) + lr;
                int bcol = kb + ((lj & 1) << 3);
                uint32_t ba = stb + brow * 80 + bcol * 2;
                ldsm_x4(bhi[g], ba + OFF_BHI);
                ldsm_x4(blo[g], ba + OFF_BLO);
            }
            uint32_t a[2][4];
            {
                int acol = kb + ((lj >> 1) << 3);
                #pragma unroll
                for (int fm = 0; fm < 2; fm++) {
                    int arow = wm * 32 + fm * 16 + ((lj & 1) << 3) + lr;
                    ldsm_x4(a[fm], stb + OFF_AHI + arow * 80 + acol * 2);
                }
            }
            #pragma unroll
            for (int fm = 0; fm < 2; fm++)
                #pragma unroll
                for (int g = 0; g < 4; g++) {
                    mma16816(acc[fm][g * 2 + 0], a[fm], bhi[g][0], bhi[g][1]);
                    mma16816(acc[fm][g * 2 + 1], a[fm], bhi[g][2], bhi[g][3]);
                    mma16816(acc[fm][g * 2 + 0], a[fm], blo[g][0], blo[g][1]);
                    mma16816(acc[fm][g * 2 + 1], a[fm], blo[g][2], blo[g][3]);
                }
            {
                int acol = kb + ((lj >> 1) << 3);
                #pragma unroll
                for (int fm = 0; fm < 2; fm++) {
                    int arow = wm * 32 + fm * 16 + ((lj & 1) << 3) + lr;
                    ldsm_x4(a[fm], stb + OFF_ALO + arow * 80 + acol * 2);
                }
            }
            #pragma unroll
            for (int fm = 0; fm < 2; fm++)
                #pragma unroll
                for (int g = 0; g < 4; g++) {
                    mma16816(acc[fm][g * 2 + 0], a[fm], bhi[g][0], bhi[g][1]);
                    mma16816(acc[fm][g * 2 + 1], a[fm], bhi[g][2], bhi[g][3]);
                }
        }
        __syncthreads();
    }

    // ---- epilogue --------------------------------------------------------
    const int qrow = lane >> 2;
    const int qcol = (lane & 3) * 2;
    #pragma unroll
    for (int fm = 0; fm < 2; fm++) {
        #pragma unroll
        for (int fn = 0; fn < 8; fn++) {
            int col = n0 + wn * 64 + fn * 8 + qcol;
            float2 bv = *(const float2*)&bias[col];
            #pragma unroll
            for (int half = 0; half < 2; half++) {
                int gm = m0 + wm * 32 + fm * 16 + qrow + half * 8;
                float x = (acc[fm][fn][half * 2 + 0] + bv.x) * scale;
                float y = (acc[fm][fn][half * 2 + 1] + bv.y) * scale;
                if (ohi) {
                    int b = gm >> 11, ss = gm & 2047;
                    int h = col >> 6, d = col & 63;
                    size_t off = (size_t)z * ACT_SLAB +
                                 (((size_t)(b * NHEADS + h)) * SEQ + ss) * DK + d;
                    uint32_t ph, pl;
                    split2(x, y, ph, pl);
                    *(uint32_t*)&ohi[off] = ph;
                    *(uint32_t*)&olo[off] = pl;
                } else {
                    *(float2*)&outp[(size_t)gm * D_MODEL + col] = make_float2(x, y);
                }
            }
        }
    }
}

// ---------------------------------------------------------------------------
// Tensor-core flash attention, bf16x3. CTA: 128 q rows, 8 warps.
// KV tiles of 64 keys, double-buffered; 2 CTAs/SM (96KB smem, <=128 regs).
// Scores arrive pre-scaled by 1/sqrt(DK)*log2(e) -> softmax in base-2.
// SMEM: Qhi 16K | Qlo 16K | 2 x (Khi 8K | Klo 8K | Vhi 8K | Vlo 8K)
// ---------------------------------------------------------------------------
#define AQ_HI 0
#define AQ_LO 16384
#define AKV0  32768
#define KVBUF 32768
#define ATT_SMEM (AKV0 + 2 * KVBUF)   // 98304

__global__ __launch_bounds__(256, 2) void attn_mma(
    const __nv_bfloat16* __restrict__ phi_, const __nv_bfloat16* __restrict__ plo_,
    __nv_bfloat16* __restrict__ chi_, __nv_bfloat16* __restrict__ clo_)
{
    extern __shared__ char smem[];
    const uint32_t sb = smem_to_u32(smem);
    const int tid = threadIdx.x, wid = tid >> 5, lane = tid & 31;
    const int bh = blockIdx.y;
    const int q0 = blockIdx.x * 128;
    const size_t base = (size_t)bh * SEQ * DK;

    const uint4* gqh = (const uint4*)(phi_ + base);
    const uint4* gql = (const uint4*)(plo_ + base);
    const uint4* gkh = (const uint4*)(phi_ + ACT_SLAB + base);
    const uint4* gkl = (const uint4*)(plo_ + ACT_SLAB + base);
    const uint4* gvh = (const uint4*)(phi_ + 2 * ACT_SLAB + base);
    const uint4* gvl = (const uint4*)(plo_ + 2 * ACT_SLAB + base);

    // --- prologue: Q tile (128 rows x 8 chunks, swizzled) -------------------
    #pragma unroll
    for (int i = 0; i < 4; i++) {
        int id = tid + i * 256;
        int r = id >> 3, c = id & 7;
        uint32_t d = sb + AQ_HI + r * 128 + ((c ^ (r & 7)) << 4);
        size_t src = (size_t)(q0 + r) * 8 + c;
        cp_async16(d, gqh + src);
        cp_async16(d + (AQ_LO - AQ_HI), gql + src);
    }
    CP_COMMIT();

    auto kv_load = [&](int s) {
        uint32_t dst0 = sb + AKV0 + (uint32_t)(s & 1) * KVBUF;
        int kvb = s * 64;
        #pragma unroll
        for (int i = 0; i < 2; i++) {
            int id = tid + i * 256;
            int r = id >> 3, c = id & 7;
            uint32_t d = dst0 + r * 128 + ((c ^ (r & 7)) << 4);
            size_t src = (size_t)(kvb + r) * 8 + c;
            cp_async16(d,         gkh + src);
            cp_async16(d + 8192,  gkl + src);
            cp_async16(d + 16384, gvh + src);
            cp_async16(d + 24576, gvl + src);
        }
        CP_COMMIT();
    };

    kv_load(0);
    CP_WAIT(1);          // Q complete
    __syncthreads();

    // --- Q-hi fragments stay in regs; Q-lo reloaded per k-tick --------------
    uint32_t qh[4][4];
    const int qw = wid * 16;
    const int qr = qw + ((lane >> 3) & 1) * 8 + (lane & 7);
    #pragma unroll
    for (int kt = 0; kt < 4; kt++) {
        int c = 2 * kt + ((lane >> 4) & 1);
        ldsm_x4(qh[kt], sb + AQ_HI + qr * 128 + ((c ^ (qr & 7)) << 4));
    }

    float o[8][4];
    #pragma unroll
    for (int j = 0; j < 8; j++)
        #pragma unroll
        for (int e = 0; e < 4; e++) o[j][e] = 0.0f;
    float mrow[2] = {-1e30f, -1e30f};
    float lrow[2] = {0.0f, 0.0f};

    const int NITER = SEQ / 64;   // 32
    for (int s = 0; s < NITER; s++) {
        if (s + 1 < NITER) { kv_load(s + 1); CP_WAIT(1); }
        else               { CP_WAIT(0); }
        __syncthreads();

        const uint32_t kb = sb + AKV0 + (uint32_t)(s & 1) * KVBUF;

        // ---- scores: S[16 x 64] = Qhi Khi^T + Qlo Khi^T + Qhi Klo^T -------
        float sc[8][4];
        #pragma unroll
        for (int j = 0; j < 8; j++)
            #pragma unroll
            for (int e = 0; e < 4; e++) sc[j][e] = 0.0f;

        #pragma unroll
        for (int kt = 0; kt < 4; kt++) {
            uint32_t qlf[4];
            {
                int c = 2 * kt + ((lane >> 4) & 1);
                ldsm_x4(qlf, sb + AQ_LO + qr * 128 + ((c ^ (qr & 7)) << 4));
            }
            #pragma unroll
            for (int g = 0; g < 4; g++) {
                int r = 16 * g + ((lane >> 4) & 1) * 8 + (lane & 7);
                int c = 2 * kt + ((lane >> 3) & 1);
                uint32_t ad = kb + r * 128 + ((c ^ (r & 7)) << 4);
                uint32_t f[4];
                ldsm_x4(f, ad);                 // Khi
                mma16816(sc[2 * g + 0], qh[kt], f[0], f[1]);
                mma16816(sc[2 * g + 1], qh[kt], f[2], f[3]);
                mma16816(sc[2 * g + 0], qlf,    f[0], f[1]);
                mma16816(sc[2 * g + 1], qlf,    f[2], f[3]);
                ldsm_x4(f, ad + 8192);          // Klo
                mma16816(sc[2 * g + 0], qh[kt], f[0], f[1]);
                mma16816(sc[2 * g + 1], qh[kt], f[2], f[3]);
            }
        }

        // ---- online softmax (base-2 domain) --------------------------------
        #pragma unroll
        for (int h = 0; h < 2; h++) {
            float mloc = -1e30f;
            #pragma unroll
            for (int j = 0; j < 8; j++)
                mloc = fmaxf(mloc, fmaxf(sc[j][2 * h], sc[j][2 * h + 1]));
            mloc = fmaxf(mloc, __shfl_xor_sync(0xffffffffu, mloc, 1));
            mloc = fmaxf(mloc, __shfl_xor_sync(0xffffffffu, mloc, 2));
            float mnew = fmaxf(mrow[h], mloc);
            float corr = ex2(mrow[h] - mnew);
            float ls = 0.0f;
            #pragma unroll
            for (int j = 0; j < 8; j++) {
                float p0 = ex2(sc[j][2 * h]     - mnew);
                float p1 = ex2(sc[j][2 * h + 1] - mnew);
                sc[j][2 * h] = p0; sc[j][2 * h + 1] = p1;
                ls += p0 + p1;
            }
            ls += __shfl_xor_sync(0xffffffffu, ls, 1);
            ls += __shfl_xor_sync(0xffffffffu, ls, 2);
            lrow[h] = lrow[h] * corr + ls;
            mrow[h] = mnew;
            #pragma unroll
            for (int j = 0; j < 8; j++) {
                o[j][2 * h] *= corr; o[j][2 * h + 1] *= corr;
            }
        }

        // ---- O += Phi Vhi + Plo Vhi + Phi Vlo ------------------------------
        #pragma unroll
        for (int kt = 0; kt < 4; kt++) {
            uint32_t pah[4], pal[4];
            split2(sc[2 * kt][0],     sc[2 * kt][1],     pah[0], pal[0]);
            split2(sc[2 * kt][2],     sc[2 * kt][3],     pah[1], pal[1]);
            split2(sc[2 * kt + 1][0], sc[2 * kt + 1][1], pah[2], pal[2]);
            split2(sc[2 * kt + 1][2], sc[2 * kt + 1][3], pah[3], pal[3]);
            #pragma unroll
            for (int g = 0; g < 4; g++) {
                int r = 16 * kt + ((lane >> 3) & 1) * 8 + (lane & 7);
                int c = 2 * g + ((lane >> 4) & 1);
                uint32_t ad = kb + 16384 + r * 128 + ((c ^ (r & 7)) << 4);
                uint32_t f[4];
                ldsm_x4_t(f, ad);               // Vhi (transposed)
                mma16816(o[2 * g + 0], pah, f[0], f[1]);
                mma16816(o[2 * g + 1], pah, f[2], f[3]);
                mma16816(o[2 * g + 0], pal, f[0], f[1]);
                mma16816(o[2 * g + 1], pal, f[2], f[3]);
                ldsm_x4_t(f, ad + 8192);        // Vlo
                mma16816(o[2 * g + 0], pah, f[0], f[1]);
                mma16816(o[2 * g + 1], pah, f[2], f[3]);
            }
        }
        __syncthreads();
    }

    // ---- epilogue: normalize, split to bf16 hi/lo ctx [M, D] ---------------
    const int b = bh >> 4;
    const int h = bh & 15;
    #pragma unroll
    for (int half = 0; half < 2; half++) {
        float inv = 1.0f / lrow[half];
        int gr = q0 + qw + (lane >> 2) + half * 8;
        size_t rowoff = ((size_t)(b * SEQ + gr)) * D_MODEL + h * DK;
        #pragma unroll
        for (int j = 0; j < 8; j++) {
            float x = o[j][2 * half]     * inv;
            float y = o[j][2 * half + 1] * inv;
            uint32_t ph, pl;
            split2(x, y, ph, pl);
            int col = j * 8 + (lane & 3) * 2;
            *(uint32_t*)&chi_[rowoff + col] = ph;
            *(uint32_t*)&clo_[rowoff + col] = pl;
        }
    }
}

// ---------------------------------------------------------------------------
extern "C" void kernel_launch(void* const* d_in, const int* in_sizes, int n_in,
                              void* d_out, int out_size)
{
    const float* q  = (const float*)d_in[0];
    const float* k  = (const float*)d_in[1];
    const float* v  = (const float*)d_in[2];
    const float* Wq = (const float*)d_in[3];
    const float* bq = (const float*)d_in[4];
    const float* Wk = (const float*)d_in[5];
    const float* bk = (const float*)d_in[6];
    const float* Wv = (const float*)d_in[7];
    const float* bv = (const float*)d_in[8];
    const float* Wo = (const float*)d_in[9];
    const float* bo = (const float*)d_in[10];
    float* out = (float*)d_out;

    __nv_bfloat16 *ahi, *alo, *whi, *wlo, *phi, *plo, *chi, *clo;
    cudaGetSymbolAddress((void**)&ahi, g_ahi);
    cudaGetSymbolAddress((void**)&alo, g_alo);
    cudaGetSymbolAddress((void**)&whi, g_whi);
    cudaGetSymbolAddress((void**)&wlo, g_wlo);
    cudaGetSymbolAddress((void**)&phi, g_phi);
    cudaGetSymbolAddress((void**)&plo, g_plo);
    cudaGetSymbolAddress((void**)&chi, g_chi);
    cudaGetSymbolAddress((void**)&clo, g_clo);

    const int actN4 = MTOT * D_MODEL / 4;
    const size_t gemmSmem = 2 * GSTAGE;

    cudaFuncSetAttribute(gemm_mma, cudaFuncAttributeMaxDynamicSharedMemorySize, (int)gemmSmem);
    cudaFuncSetAttribute(attn_mma, cudaFuncAttributeMaxDynamicSharedMemorySize, ATT_SMEM);

    // 1) Convert all weights and activations
    conv_wt_all<<<dim3(D_MODEL / 32, D_MODEL / 32, 4), dim3(32, 32)>>>(
        Wq, Wk, Wv, Wo, whi, wlo);
    conv_split_all<<<dim3(actN4 / 256, 3), 256>>>(
        (const float4*)q, (const float4*)k, (const float4*)v, ahi, alo);

    // 2) Q/K/V projections, one batched launch.
    //    Q pre-scaled by 1/sqrt(DK) * log2(e) for base-2 softmax.
    gemm_mma<<<dim3(D_MODEL / 128, MTOT / 128, 3), 256, gemmSmem>>>(
        ahi, alo, whi, wlo, bq, bk, bv, nullptr, phi, plo, 0.18033688011112042f);

    // 3) Attention (tensor cores, 2 CTAs/SM)
    attn_mma<<<dim3(SEQ / 128, BATCH * NHEADS), 256, ATT_SMEM>>>(phi, plo, chi, clo);

    // 4) Output projection (fp32 out). Wo slab = index 3.
    gemm_mma<<<dim3(D_MODEL / 128, MTOT / 128, 1), 256, gemmSmem>>>(
        chi, clo, whi + 3 * W_SLAB, wlo + 3 * W_SLAB,
        bo, bo, bo, out, nullptr, nullptr, 1.0f);
}

// round 7
// speedup vs baseline: 2.9364x; 1.0164x over previous
#include <cuda_runtime.h>
#include <cuda_bf16.h>
#include <cstdint>

#define D_MODEL 1024
#define NHEADS  16
#define DK      64
#define BATCH   2
#define SEQ     2048
#define MTOT    (BATCH * SEQ)   // 4096

#define ACT_SLAB ((size_t)MTOT * D_MODEL)      // 4M elements
#define W_SLAB   ((size_t)D_MODEL * D_MODEL)   // 1M elements

// ---------------------------------------------------------------------------
// Scratch (device globals — no allocation allowed)
// ---------------------------------------------------------------------------
__device__ __nv_bfloat16 g_ahi[3 * ACT_SLAB];  // activation splits (q,k,v)
__device__ __nv_bfloat16 g_alo[3 * ACT_SLAB];
__device__ __nv_bfloat16 g_whi[4 * W_SLAB];    // W^T splits (Wq,Wk,Wv,Wo) [N,K]
__device__ __nv_bfloat16 g_wlo[4 * W_SLAB];

__device__ __nv_bfloat16 g_phi[3 * ACT_SLAB];  // projected q/k/v hi [B,H,S,DK]
__device__ __nv_bfloat16 g_plo[3 * ACT_SLAB];
__device__ __nv_bfloat16 g_chi[ACT_SLAB];      // ctx split [M, D]
__device__ __nv_bfloat16 g_clo[ACT_SLAB];

// ---------------------------------------------------------------------------
// helpers
// ---------------------------------------------------------------------------
__device__ __forceinline__ uint32_t smem_to_u32(const void* p) {
    uint32_t a;
    asm("{ .reg .u64 t; cvta.to.shared.u64 t, %1; cvt.u32.u64 %0, t; }"
        : "=r"(a) : "l"(p));
    return a;
}
__device__ __forceinline__ void cp_async16(uint32_t dst, const void* src) {
    asm volatile("cp.async.cg.shared.global [%0], [%1], 16;"
                 :: "r"(dst), "l"(src) : "memory");
}
#define CP_COMMIT() asm volatile("cp.async.commit_group;" ::: "memory")
#define CP_WAIT(n)  asm volatile("cp.async.wait_group %0;" :: "n"(n) : "memory")

__device__ __forceinline__ void ldsm_x4(uint32_t* d, uint32_t addr) {
    asm volatile("ldmatrix.sync.aligned.m8n8.x4.shared.b16 {%0,%1,%2,%3}, [%4];"
                 : "=r"(d[0]), "=r"(d[1]), "=r"(d[2]), "=r"(d[3]) : "r"(addr));
}
__device__ __forceinline__ void ldsm_x4_t(uint32_t* d, uint32_t addr) {
    asm volatile("ldmatrix.sync.aligned.m8n8.x4.trans.shared.b16 {%0,%1,%2,%3}, [%4];"
                 : "=r"(d[0]), "=r"(d[1]), "=r"(d[2]), "=r"(d[3]) : "r"(addr));
}
__device__ __forceinline__ void mma16816(float* c, const uint32_t* a,
                                         uint32_t b0, uint32_t b1) {
    asm volatile(
        "mma.sync.aligned.m16n8k16.row.col.f32.bf16.bf16.f32 "
        "{%0,%1,%2,%3}, {%4,%5,%6,%7}, {%8,%9}, {%0,%1,%2,%3};"
        : "+f"(c[0]), "+f"(c[1]), "+f"(c[2]), "+f"(c[3])
        : "r"(a[0]), "r"(a[1]), "r"(a[2]), "r"(a[3]), "r"(b0), "r"(b1));
}
// split (x,y) -> packed bf16 hi/lo pairs (low half = x). Packed-cvt version:
// same RN rounding as __float2bfloat16, 6 instrs instead of ~10.
__device__ __forceinline__ void split2(float x, float y, uint32_t& hi, uint32_t& lo) {
    uint32_t h;
    asm("cvt.rn.bf16x2.f32 %0, %1, %2;" : "=r"(h) : "f"(y), "f"(x));
    float hx = __uint_as_float(h << 16);
    float hy = __uint_as_float(h & 0xFFFF0000u);
    uint32_t l;
    asm("cvt.rn.bf16x2.f32 %0, %1, %2;" : "=r"(l) : "f"(y - hy), "f"(x - hx));
    hi = h; lo = l;
}
__device__ __forceinline__ float ex2(float x) {
    float y;
    asm("ex2.approx.ftz.f32 %0, %1;" : "=f"(y) : "f"(x));
    return y;
}

// ---------------------------------------------------------------------------
// fp32 -> bf16 hi/lo split, all 3 activations in one launch (y = input idx)
// ---------------------------------------------------------------------------
__global__ __launch_bounds__(256) void conv_split_all(
    const float4* __restrict__ x0, const float4* __restrict__ x1,
    const float4* __restrict__ x2,
    __nv_bfloat16* __restrict__ hi, __nv_bfloat16* __restrict__ lo)
{
    const int z = blockIdx.y;
    const float4* x = z == 0 ? x0 : (z == 1 ? x1 : x2);
    int i = blockIdx.x * 256 + threadIdx.x;
    float4 v = x[i];
    uint32_t h0, l0, h1, l1;
    split2(v.x, v.y, h0, l0);
    split2(v.z, v.w, h1, l1);
    size_t off = (size_t)z * ACT_SLAB + (size_t)i * 4;
    *(uint2*)&hi[off] = make_uint2(h0, h1);
    *(uint2*)&lo[off] = make_uint2(l0, l1);
}

// All 4 weights: W [K,N] fp32 -> W^T [N,K] bf16 hi/lo (z = weight idx)
__global__ __launch_bounds__(1024) void conv_wt_all(
    const float* __restrict__ W0, const float* __restrict__ W1,
    const float* __restrict__ W2, const float* __restrict__ W3,
    __nv_bfloat16* __restrict__ hi, __nv_bfloat16* __restrict__ lo)
{
    __shared__ float t[32][33];
    const int z = blockIdx.z;
    const float* W = z == 0 ? W0 : (z == 1 ? W1 : (z == 2 ? W2 : W3));
    int tx = threadIdx.x, ty = threadIdx.y;
    int n0 = blockIdx.x * 32, k0 = blockIdx.y * 32;
    t[ty][tx] = W[(size_t)(k0 + ty) * D_MODEL + n0 + tx];
    __syncthreads();
    float v = t[tx][ty];
    __nv_bfloat16 h = __float2bfloat16(v);
    size_t o = (size_t)z * W_SLAB + (size_t)(n0 + ty) * D_MODEL + k0 + tx;
    hi[o] = h;
    lo[o] = __float2bfloat16(v - __bfloat162float(h));
}

// ---------------------------------------------------------------------------
// bf16x3 tensor-core GEMM (batched over blockIdx.z). 2 CTAs/SM.
// Inner tick sequenced to keep live fragments low:
//   Bhi -> Ahi*Bhi, Alo*Bhi; overwrite with Blo -> Ahi*Blo.
// ---------------------------------------------------------------------------
#define GSTAGE 40960
#define OFF_AHI 0
#define OFF_ALO 10240
#define OFF_BHI 20480
#define OFF_BLO 30720
#define NSTAGES 32

__global__ __launch_bounds__(256, 2) void gemm_mma(
    const __nv_bfloat16* __restrict__ a_hi, const __nv_bfloat16* __restrict__ a_lo,
    const __nv_bfloat16* __restrict__ w_hi, const __nv_bfloat16* __restrict__ w_lo,
    const float* __restrict__ b0, const float* __restrict__ b1,
    const float* __restrict__ b2,
    float* __restrict__ outp,
    __nv_bfloat16* __restrict__ ohi, __nv_bfloat16* __restrict__ olo,
    float scale0)
{
    extern __shared__ char smem[];
    const uint32_t sbase = smem_to_u32(smem);
    const int tid  = threadIdx.x;
    const int wid  = tid >> 5;
    const int lane = tid & 31;
    const int wm = wid >> 1;
    const int wn = wid & 1;
    const int m0 = blockIdx.y * 128;
    const int n0 = blockIdx.x * 128;
    const int z  = blockIdx.z;
    const float* bias = z == 0 ? b0 : (z == 1 ? b1 : b2);
    const float scale = z == 0 ? scale0 : 1.0f;

    const uint4* gAhi = (const uint4*)(a_hi + (size_t)z * ACT_SLAB);
    const uint4* gAlo = (const uint4*)(a_lo + (size_t)z * ACT_SLAB);
    const uint4* gBhi = (const uint4*)(w_hi + (size_t)z * W_SLAB);
    const uint4* gBlo = (const uint4*)(w_lo + (size_t)z * W_SLAB);

    auto load_stage = [&](int s) {
        const uint32_t stb = sbase + (uint32_t)(s & 1) * GSTAGE;
        const int koff4 = s * 4;
        #pragma unroll
        for (int t = 0; t < 2; t++) {
            int id = tid + (t << 8);
            int row = id >> 2;
            int c   = id & 3;
            uint32_t d = stb + row * 80 + c * 16;
            size_t srcA = (size_t)(m0 + row) * 128 + koff4 + c;
            size_t srcB = (size_t)(n0 + row) * 128 + koff4 + c;
            cp_async16(d + OFF_AHI, gAhi + srcA);
            cp_async16(d + OFF_ALO, gAlo + srcA);
            cp_async16(d + OFF_BHI, gBhi + srcB);
            cp_async16(d + OFF_BLO, gBlo + srcB);
        }
        CP_COMMIT();
    };

    float acc[2][8][4];
    #pragma unroll
    for (int i = 0; i < 2; i++)
        #pragma unroll
        for (int j = 0; j < 8; j++)
            #pragma unroll
            for (int e = 0; e < 4; e++) acc[i][j][e] = 0.0f;

    const int lj = lane >> 3;
    const int lr = lane & 7;

    load_stage(0);

    for (int s = 0; s < NSTAGES; s++) {
        if (s + 1 < NSTAGES) load_stage(s + 1);
        if (s + 1 < NSTAGES) { CP_WAIT(1); } else { CP_WAIT(0); }
        __syncthreads();

        const uint32_t stb = sbase + (uint32_t)(s & 1) * GSTAGE;

        #pragma unroll
        for (int t = 0; t < 2; t++) {
            const int kb = t * 16;
            const int acol = kb + ((lj >> 1) << 3);
            const int bcol = kb + ((lj & 1) << 3);

            // B-hi fragments (reused by Ahi and Alo passes)
            uint32_t bf[4][4];
            #pragma unroll
            for (int g = 0; g < 4; g++) {
                int brow = wn * 64 + g * 16 + ((lj >> 1) << 3) + lr;
                ldsm_x4(bf[g], stb + OFF_BHI + brow * 80 + bcol * 2);
            }
            // A-hi pass
            uint32_t ah[2][4];
            #pragma unroll
            for (int fm = 0; fm < 2; fm++) {
                int arow = wm * 32 + fm * 16 + ((lj & 1) << 3) + lr;
                ldsm_x4(ah[fm], stb + OFF_AHI + arow * 80 + acol * 2);
            }
            #pragma unroll
            for (int fm = 0; fm < 2; fm++)
                #pragma unroll
                for (int g = 0; g < 4; g++) {
                    mma16816(acc[fm][g * 2 + 0], ah[fm], bf[g][0], bf[g][1]);
                    mma16816(acc[fm][g * 2 + 1], ah[fm], bf[g][2], bf[g][3]);
                }
            // A-lo pass (against B-hi)
            {
                uint32_t al[2][4];
                #pragma unroll
                for (int fm = 0; fm < 2; fm++) {
                    int arow = wm * 32 + fm * 16 + ((lj & 1) << 3) + lr;
                    ldsm_x4(al[fm], stb + OFF_ALO + arow * 80 + acol * 2);
                }
                #pragma unroll
                for (int fm = 0; fm < 2; fm++)
                    #pragma unroll
                    for (int g = 0; g < 4; g++) {
                        mma16816(acc[fm][g * 2 + 0], al[fm], bf[g][0], bf[g][1]);
                        mma16816(acc[fm][g * 2 + 1], al[fm], bf[g][2], bf[g][3]);
                    }
            }
            // B-lo pass (overwrite bf; against A-hi)
            #pragma unroll
            for (int g = 0; g < 4; g++) {
                int brow = wn * 64 + g * 16 + ((lj >> 1) << 3) + lr;
                ldsm_x4(bf[g], stb + OFF_BLO + brow * 80 + bcol * 2);
            }
            #pragma unroll
            for (int fm = 0; fm < 2; fm++)
                #pragma unroll
                for (int g = 0; g < 4; g++) {
                    mma16816(acc[fm][g * 2 + 0], ah[fm], bf[g][0], bf[g][1]);
                    mma16816(acc[fm][g * 2 + 1], ah[fm], bf[g][2], bf[g][3]);
                }
        }
        __syncthreads();
    }

    // ---- epilogue --------------------------------------------------------
    const int qrow = lane >> 2;
    const int qcol = (lane & 3) * 2;
    #pragma unroll
    for (int fm = 0; fm < 2; fm++) {
        #pragma unroll
        for (int fn = 0; fn < 8; fn++) {
            int col = n0 + wn * 64 + fn * 8 + qcol;
            float2 bv = *(const float2*)&bias[col];
            #pragma unroll
            for (int half = 0; half < 2; half++) {
                int gm = m0 + wm * 32 + fm * 16 + qrow + half * 8;
                float x = (acc[fm][fn][half * 2 + 0] + bv.x) * scale;
                float y = (acc[fm][fn][half * 2 + 1] + bv.y) * scale;
                if (ohi) {
                    int b = gm >> 11, ss = gm & 2047;
                    int h = col >> 6, d = col & 63;
                    size_t off = (size_t)z * ACT_SLAB +
                                 (((size_t)(b * NHEADS + h)) * SEQ + ss) * DK + d;
                    uint32_t ph, pl;
                    split2(x, y, ph, pl);
                    *(uint32_t*)&ohi[off] = ph;
                    *(uint32_t*)&olo[off] = pl;
                } else {
                    *(float2*)&outp[(size_t)gm * D_MODEL + col] = make_float2(x, y);
                }
            }
        }
    }
}

// ---------------------------------------------------------------------------
// Tensor-core flash attention, bf16x3. CTA: 128 q rows, 8 warps.
// KV tiles of 64 keys, double-buffered; 2 CTAs/SM.
// Scores arrive pre-scaled by 1/sqrt(DK)*log2(e) -> softmax in base-2.
// ---------------------------------------------------------------------------
#define AQ_HI 0
#define AQ_LO 16384
#define AKV0  32768
#define KVBUF 32768
#define ATT_SMEM (AKV0 + 2 * KVBUF)   // 98304

__global__ __launch_bounds__(256, 2) void attn_mma(
    const __nv_bfloat16* __restrict__ phi_, const __nv_bfloat16* __restrict__ plo_,
    __nv_bfloat16* __restrict__ chi_, __nv_bfloat16* __restrict__ clo_)
{
    extern __shared__ char smem[];
    const uint32_t sb = smem_to_u32(smem);
    const int tid = threadIdx.x, wid = tid >> 5, lane = tid & 31;
    const int bh = blockIdx.y;
    const int q0 = blockIdx.x * 128;
    const size_t base = (size_t)bh * SEQ * DK;

    const uint4* gqh = (const uint4*)(phi_ + base);
    const uint4* gql = (const uint4*)(plo_ + base);
    const uint4* gkh = (const uint4*)(phi_ + ACT_SLAB + base);
    const uint4* gkl = (const uint4*)(plo_ + ACT_SLAB + base);
    const uint4* gvh = (const uint4*)(phi_ + 2 * ACT_SLAB + base);
    const uint4* gvl = (const uint4*)(plo_ + 2 * ACT_SLAB + base);

    // --- prologue: Q tile (128 rows x 8 chunks, swizzled) -------------------
    #pragma unroll
    for (int i = 0; i < 4; i++) {
        int id = tid + i * 256;
        int r = id >> 3, c = id & 7;
        uint32_t d = sb + AQ_HI + r * 128 + ((c ^ (r & 7)) << 4);
        size_t src = (size_t)(q0 + r) * 8 + c;
        cp_async16(d, gqh + src);
        cp_async16(d + (AQ_LO - AQ_HI), gql + src);
    }
    CP_COMMIT();

    auto kv_load = [&](int s) {
        uint32_t dst0 = sb + AKV0 + (uint32_t)(s & 1) * KVBUF;
        int kvb = s * 64;
        #pragma unroll
        for (int i = 0; i < 2; i++) {
            int id = tid + i * 256;
            int r = id >> 3, c = id & 7;
            uint32_t d = dst0 + r * 128 + ((c ^ (r & 7)) << 4);
            size_t src = (size_t)(kvb + r) * 8 + c;
            cp_async16(d,         gkh + src);
            cp_async16(d + 8192,  gkl + src);
            cp_async16(d + 16384, gvh + src);
            cp_async16(d + 24576, gvl + src);
        }
        CP_COMMIT();
    };

    kv_load(0);
    CP_WAIT(1);          // Q complete
    __syncthreads();

    // --- Q-hi fragments stay in regs; Q-lo reloaded per k-tick --------------
    uint32_t qh[4][4];
    const int qw = wid * 16;
    const int qr = qw + ((lane >> 3) & 1) * 8 + (lane & 7);
    #pragma unroll
    for (int kt = 0; kt < 4; kt++) {
        int c = 2 * kt + ((lane >> 4) & 1);
        ldsm_x4(qh[kt], sb + AQ_HI + qr * 128 + ((c ^ (qr & 7)) << 4));
    }

    float o[8][4];
    #pragma unroll
    for (int j = 0; j < 8; j++)
        #pragma unroll
        for (int e = 0; e < 4; e++) o[j][e] = 0.0f;
    float mrow[2] = {-1e30f, -1e30f};
    float lrow[2] = {0.0f, 0.0f};

    const int NITER = SEQ / 64;   // 32
    for (int s = 0; s < NITER; s++) {
        if (s + 1 < NITER) { kv_load(s + 1); CP_WAIT(1); }
        else               { CP_WAIT(0); }
        __syncthreads();

        const uint32_t kb = sb + AKV0 + (uint32_t)(s & 1) * KVBUF;

        // ---- scores: S[16 x 64] = Qhi Khi^T + Qlo Khi^T + Qhi Klo^T -------
        float sc[8][4];
        #pragma unroll
        for (int j = 0; j < 8; j++)
            #pragma unroll
            for (int e = 0; e < 4; e++) sc[j][e] = 0.0f;

        #pragma unroll
        for (int kt = 0; kt < 4; kt++) {
            uint32_t qlf[4];
            {
                int c = 2 * kt + ((lane >> 4) & 1);
                ldsm_x4(qlf, sb + AQ_LO + qr * 128 + ((c ^ (qr & 7)) << 4));
            }
            #pragma unroll
            for (int g = 0; g < 4; g++) {
                int r = 16 * g + ((lane >> 4) & 1) * 8 + (lane & 7);
                int c = 2 * kt + ((lane >> 3) & 1);
                uint32_t ad = kb + r * 128 + ((c ^ (r & 7)) << 4);
                uint32_t f[4];
                ldsm_x4(f, ad);                 // Khi
                mma16816(sc[2 * g + 0], qh[kt], f[0], f[1]);
                mma16816(sc[2 * g + 1], qh[kt], f[2], f[3]);
                mma16816(sc[2 * g + 0], qlf,    f[0], f[1]);
                mma16816(sc[2 * g + 1], qlf,    f[2], f[3]);
                ldsm_x4(f, ad + 8192);          // Klo
                mma16816(sc[2 * g + 0], qh[kt], f[0], f[1]);
                mma16816(sc[2 * g + 1], qh[kt], f[2], f[3]);
            }
        }

        // ---- online softmax (base-2 domain) --------------------------------
        #pragma unroll
        for (int h = 0; h < 2; h++) {
            float mloc = -1e30f;
            #pragma unroll
            for (int j = 0; j < 8; j++)
                mloc = fmaxf(mloc, fmaxf(sc[j][2 * h], sc[j][2 * h + 1]));
            mloc = fmaxf(mloc, __shfl_xor_sync(0xffffffffu, mloc, 1));
            mloc = fmaxf(mloc, __shfl_xor_sync(0xffffffffu, mloc, 2));
            float mnew = fmaxf(mrow[h], mloc);
            float corr = ex2(mrow[h] - mnew);
            float ls = 0.0f;
            #pragma unroll
            for (int j = 0; j < 8; j++) {
                float p0 = ex2(sc[j][2 * h]     - mnew);
                float p1 = ex2(sc[j][2 * h + 1] - mnew);
                sc[j][2 * h] = p0; sc[j][2 * h + 1] = p1;
                ls += p0 + p1;
            }
            ls += __shfl_xor_sync(0xffffffffu, ls, 1);
            ls += __shfl_xor_sync(0xffffffffu, ls, 2);
            lrow[h] = lrow[h] * corr + ls;
            mrow[h] = mnew;
            #pragma unroll
            for (int j = 0; j < 8; j++) {
                o[j][2 * h] *= corr; o[j][2 * h + 1] *= corr;
            }
        }

        // ---- O += Phi Vhi + Plo Vhi + Phi Vlo ------------------------------
        #pragma unroll
        for (int kt = 0; kt < 4; kt++) {
            uint32_t pah[4], pal[4];
            split2(sc[2 * kt][0],     sc[2 * kt][1],     pah[0], pal[0]);
            split2(sc[2 * kt][2],     sc[2 * kt][3],     pah[1], pal[1]);
            split2(sc[2 * kt + 1][0], sc[2 * kt + 1][1], pah[2], pal[2]);
            split2(sc[2 * kt + 1][2], sc[2 * kt + 1][3], pah[3], pal[3]);
            #pragma unroll
            for (int g = 0; g < 4; g++) {
                int r = 16 * kt + ((lane >> 3) & 1) * 8 + (lane & 7);
                int c = 2 * g + ((lane >> 4) & 1);
                uint32_t ad = kb + 16384 + r * 128 + ((c ^ (r & 7)) << 4);
                uint32_t f[4];
                ldsm_x4_t(f, ad);               // Vhi (transposed)
                mma16816(o[2 * g + 0], pah, f[0], f[1]);
                mma16816(o[2 * g + 1], pah, f[2], f[3]);
                mma16816(o[2 * g + 0], pal, f[0], f[1]);
                mma16816(o[2 * g + 1], pal, f[2], f[3]);
                ldsm_x4_t(f, ad + 8192);        // Vlo
                mma16816(o[2 * g + 0], pah, f[0], f[1]);
                mma16816(o[2 * g + 1], pah, f[2], f[3]);
            }
        }
        __syncthreads();
    }

    // ---- epilogue: normalize, split to bf16 hi/lo ctx [M, D] ---------------
    const int b = bh >> 4;
    const int h = bh & 15;
    #pragma unroll
    for (int half = 0; half < 2; half++) {
        float inv = 1.0f / lrow[half];
        int gr = q0 + qw + (lane >> 2) + half * 8;
        size_t rowoff = ((size_t)(b * SEQ + gr)) * D_MODEL + h * DK;
        #pragma unroll
        for (int j = 0; j < 8; j++) {
            float x = o[j][2 * half]     * inv;
            float y = o[j][2 * half + 1] * inv;
            uint32_t ph, pl;
            split2(x, y, ph, pl);
            int col = j * 8 + (lane & 3) * 2;
            *(uint32_t*)&chi_[rowoff + col] = ph;
            *(uint32_t*)&clo_[rowoff + col] = pl;
        }
    }
}

// ---------------------------------------------------------------------------
extern "C" void kernel_launch(void* const* d_in, const int* in_sizes, int n_in,
                              void* d_out, int out_size)
{
    const float* q  = (const float*)d_in[0];
    const float* k  = (const float*)d_in[1];
    const float* v  = (const float*)d_in[2];
    const float* Wq = (const float*)d_in[3];
    const float* bq = (const float*)d_in[4];
    const float* Wk = (const float*)d_in[5];
    const float* bk = (const float*)d_in[6];
    const float* Wv = (const float*)d_in[7];
    const float* bv = (const float*)d_in[8];
    const float* Wo = (const float*)d_in[9];
    const float* bo = (const float*)d_in[10];
    float* out = (float*)d_out;

    __nv_bfloat16 *ahi, *alo, *whi, *wlo, *phi, *plo, *chi, *clo;
    cudaGetSymbolAddress((void**)&ahi, g_ahi);
    cudaGetSymbolAddress((void**)&alo, g_alo);
    cudaGetSymbolAddress((void**)&whi, g_whi);
    cudaGetSymbolAddress((void**)&wlo, g_wlo);
    cudaGetSymbolAddress((void**)&phi, g_phi);
    cudaGetSymbolAddress((void**)&plo, g_plo);
    cudaGetSymbolAddress((void**)&chi, g_chi);
    cudaGetSymbolAddress((void**)&clo, g_clo);

    const int actN4 = MTOT * D_MODEL / 4;
    const size_t gemmSmem = 2 * GSTAGE;

    cudaFuncSetAttribute(gemm_mma, cudaFuncAttributeMaxDynamicSharedMemorySize, (int)gemmSmem);
    cudaFuncSetAttribute(attn_mma, cudaFuncAttributeMaxDynamicSharedMemorySize, ATT_SMEM);

    // 1) Convert all weights and activations
    conv_wt_all<<<dim3(D_MODEL / 32, D_MODEL / 32, 4), dim3(32, 32)>>>(
        Wq, Wk, Wv, Wo, whi, wlo);
    conv_split_all<<<dim3(actN4 / 256, 3), 256>>>(
        (const float4*)q, (const float4*)k, (const float4*)v, ahi, alo);

    // 2) Q/K/V projections, one batched launch.
    //    Q pre-scaled by 1/sqrt(DK) * log2(e) for base-2 softmax.
    gemm_mma<<<dim3(D_MODEL / 128, MTOT / 128, 3), 256, gemmSmem>>>(
        ahi, alo, whi, wlo, bq, bk, bv, nullptr, phi, plo, 0.18033688011112042f);

    // 3) Attention (tensor cores, 2 CTAs/SM)
    attn_mma<<<dim3(SEQ / 128, BATCH * NHEADS), 256, ATT_SMEM>>>(phi, plo, chi, clo);

    // 4) Output projection (fp32 out). Wo slab = index 3.
    gemm_mma<<<dim3(D_MODEL / 128, MTOT / 128, 1), 256, gemmSmem>>>(
        chi, clo, whi + 3 * W_SLAB, wlo + 3 * W_SLAB,
        bo, bo, bo, out, nullptr, nullptr, 1.0f);
}